// round 10
// baseline (speedup 1.0000x reference)
#include <cuda_runtime.h>
#include <cuda_fp16.h>
#include <cuda_bf16.h>
#include <stdint.h>

// Problem constants
#define NN 100000
#define NE 1600000
#define NE2 (NE + NN)
#define SCAN_T 512
#define SCAN_TILES ((NN + SCAN_T - 1) / SCAN_T)  // 196

// ---------------------------------------------------------------------------
// Scratch (device globals — no allocation allowed)
// ---------------------------------------------------------------------------
__device__ __half g_h16[(size_t)NN * 128]; // fp16 linear output (all layers)
__device__ float  g_out[(size_t)NN * 64];  // per-layer aggregated output
__device__ float  g_asrc[NN * 8];
__device__ float  g_adst[NN * 8];
__device__ int    g_rowptr[NN + 1];
__device__ int    g_cursor[NN];
__device__ int    g_csrc[NE2];
__device__ int    g_cnt[NN];
__device__ int    g_tilesum[SCAN_TILES];
__device__ int    g_tileoff[SCAN_TILES];
// Weight transposes, bf16 hi/lo split, layout [n][k]
__device__ __nv_bfloat16 g_wh1[64 * 256], g_wl1[64 * 256];
__device__ __nv_bfloat16 g_wh2[64 * 320], g_wl2[64 * 320];
__device__ __nv_bfloat16 g_wh3[128 * 64], g_wl3[128 * 64];

// ---------------------------------------------------------------------------
// CSR build (dst-sorted adjacency incl. self-loops), reused for all 3 layers
// ---------------------------------------------------------------------------
__global__ void k_deg_init() {
    int i = blockIdx.x * blockDim.x + threadIdx.x;
    if (i < NN) g_cnt[i] = 1;  // self loop
}

__global__ void k_hist(const int* __restrict__ edst) {
    int e = blockIdx.x * blockDim.x + threadIdx.x;
    if (e < NE) atomicAdd(&g_cnt[edst[e]], 1);
}

// Coalesced two-level scan: tile reduce -> scan tile sums -> tile-local scan
__global__ __launch_bounds__(SCAN_T) void k_scan_a() {
    __shared__ int sm[SCAN_T];
    int i = blockIdx.x * SCAN_T + threadIdx.x;
    sm[threadIdx.x] = (i < NN) ? g_cnt[i] : 0;
    __syncthreads();
#pragma unroll
    for (int off = SCAN_T / 2; off > 0; off >>= 1) {
        if (threadIdx.x < off) sm[threadIdx.x] += sm[threadIdx.x + off];
        __syncthreads();
    }
    if (threadIdx.x == 0) g_tilesum[blockIdx.x] = sm[0];
}

__global__ __launch_bounds__(256) void k_scan_b() {
    __shared__ int sm[256];
    int t = threadIdx.x;
    int v = (t < SCAN_TILES) ? g_tilesum[t] : 0;
    sm[t] = v;
    __syncthreads();
#pragma unroll
    for (int off = 1; off < 256; off <<= 1) {
        int u = (t >= off) ? sm[t - off] : 0;
        __syncthreads();
        sm[t] += u;
        __syncthreads();
    }
    if (t < SCAN_TILES) g_tileoff[t] = sm[t] - v;  // exclusive prefix of tiles
    if (t == 255) g_rowptr[NN] = sm[255];
}

__global__ __launch_bounds__(SCAN_T) void k_scan_c() {
    __shared__ int sm[SCAN_T];
    int i = blockIdx.x * SCAN_T + threadIdx.x;
    int v = (i < NN) ? g_cnt[i] : 0;
    sm[threadIdx.x] = v;
    __syncthreads();
#pragma unroll
    for (int off = 1; off < SCAN_T; off <<= 1) {
        int u = (threadIdx.x >= off) ? sm[threadIdx.x - off] : 0;
        __syncthreads();
        sm[threadIdx.x] += u;
        __syncthreads();
    }
    if (i < NN) {
        int ex = g_tileoff[blockIdx.x] + sm[threadIdx.x] - v;  // exclusive
        g_rowptr[i] = ex;
        g_cursor[i] = ex;
    }
}

__global__ void k_scatter(const int* __restrict__ esrc, const int* __restrict__ edst) {
    int i = blockIdx.x * blockDim.x + threadIdx.x;
    if (i < NN) {
        int p = atomicAdd(&g_cursor[i], 1);
        g_csrc[p] = i;  // self loop
    } else if (i < NN + NE) {
        int e = i - NN;
        int d = edst[e];
        int p = atomicAdd(&g_cursor[d], 1);
        g_csrc[p] = esrc[e];
    }
}

// ---------------------------------------------------------------------------
// Weight transpose + bf16 hi/lo split: Wt[n][k] = W[k][n]
// ---------------------------------------------------------------------------
__device__ __forceinline__ void wsplit(float w, __nv_bfloat16* ph, __nv_bfloat16* pl) {
    uint32_t u = __float_as_uint(w);
    float hif = __uint_as_float(u & 0xffff0000u);
    *ph = __ushort_as_bfloat16((unsigned short)(u >> 16));
    *pl = __float2bfloat16(w - hif);
}

__global__ void k_wt(const float* __restrict__ W1, const float* __restrict__ W2,
                     const float* __restrict__ W3) {
    int i = blockIdx.x * blockDim.x + threadIdx.x;
    if (i < 64 * 256) {
        int n = i / 256, k = i % 256;
        wsplit(W1[k * 64 + n], &g_wh1[i], &g_wl1[i]);
    } else if (i < 64 * 256 + 64 * 320) {
        int j = i - 64 * 256;
        int n = j / 320, k = j % 320;
        wsplit(W2[k * 64 + n], &g_wh2[j], &g_wl2[j]);
    } else if (i < 64 * 256 + 64 * 320 + 128 * 64) {
        int j = i - 64 * 256 - 64 * 320;
        int n = j / 64, k = j % 64;
        wsplit(W3[k * 128 + n], &g_wh3[j], &g_wl3[j]);
    }
}

// ---------------------------------------------------------------------------
// mma.sync bf16 GEMM, 3-term split, M=16/warp, 128-thr CTA (64 rows),
// software-pipelined A loads. Output: h16 + fused attention dots.
// ---------------------------------------------------------------------------
#define MMA_BF16(c, a, b)                                                     \
    asm volatile(                                                             \
        "mma.sync.aligned.m16n8k16.row.col.f32.bf16.bf16.f32 "                \
        "{%0,%1,%2,%3}, {%4,%5,%6,%7}, {%8,%9}, {%0,%1,%2,%3};"               \
        : "+f"((c)[0]), "+f"((c)[1]), "+f"((c)[2]), "+f"((c)[3])              \
        : "r"((a)[0]), "r"((a)[1]), "r"((a)[2]), "r"((a)[3]),                 \
          "r"((b)[0]), "r"((b)[1]))

__device__ __forceinline__ void split2(float2 f, uint32_t& hi, uint32_t& lo) {
    uint32_t u0 = __float_as_uint(f.x), u1 = __float_as_uint(f.y);
    hi = (u0 >> 16) | (u1 & 0xffff0000u);  // packed bf16x2 (truncated)
    float l0 = f.x - __uint_as_float(u0 & 0xffff0000u);
    float l1 = f.y - __uint_as_float(u1 & 0xffff0000u);
    __nv_bfloat162 lb = __floats2bfloat162_rn(l0, l1);
    lo = *reinterpret_cast<uint32_t*>(&lb);
}

template <int CH, int HROW>
__global__ __launch_bounds__(128) void k_gemm_mma(
    const float* __restrict__ A1, int K1,
    const float* __restrict__ A2, int K2,
    const __nv_bfloat16* __restrict__ Wh,
    const __nv_bfloat16* __restrict__ Wl,
    const float* __restrict__ ats,
    const float* __restrict__ atd)
{
    int tid = threadIdx.x;
    int wid = tid >> 5, lane = tid & 31;
    int g = lane >> 2, tg = lane & 3;
    int warpRow = blockIdx.x * 64 + wid * 16;
    int colBase = blockIdx.y * 64;
    int Ktot = K1 + K2;
    int nch = Ktot >> 4;

    // clamped global rows for this lane's fragment
    int r0 = warpRow + g;      if (r0 >= NN) r0 = NN - 1;
    int r1 = warpRow + g + 8;  if (r1 >= NN) r1 = NN - 1;

    float acc[8][4];
#pragma unroll
    for (int nb = 0; nb < 8; nb++)
#pragma unroll
        for (int j = 0; j < 4; j++) acc[nb][j] = 0.f;

    float2 buf[2][4];
    auto issueA = [&](int c, float2* b) {
        int kbase = c << 4;
        const float* src; int stride, koff;
        if (kbase < K1) { src = A1; stride = K1; koff = kbase; }
        else            { src = A2; stride = K2; koff = kbase - K1; }
        const float* p0 = src + (size_t)r0 * stride + koff + tg * 2;
        const float* p1 = src + (size_t)r1 * stride + koff + tg * 2;
        b[0] = *(const float2*)p0;
        b[1] = *(const float2*)p1;
        b[2] = *(const float2*)(p0 + 8);
        b[3] = *(const float2*)(p1 + 8);
    };

    issueA(0, buf[0]);
    for (int c = 0; c < nch; c++) {
        int cur = c & 1;
        if (c + 1 < nch) issueA(c + 1, buf[cur ^ 1]);

        int kbase = c << 4;
        uint32_t bh[8][2], bl[8][2];
#pragma unroll
        for (int nb = 0; nb < 8; nb++) {
            int n = colBase + nb * 8 + g;
            size_t base = (size_t)n * Ktot + kbase + tg * 2;
            bh[nb][0] = *(const uint32_t*)(Wh + base);
            bh[nb][1] = *(const uint32_t*)(Wh + base + 8);
            bl[nb][0] = *(const uint32_t*)(Wl + base);
            bl[nb][1] = *(const uint32_t*)(Wl + base + 8);
        }

        uint32_t ah[4], al[4];
        split2(buf[cur][0], ah[0], al[0]);
        split2(buf[cur][1], ah[1], al[1]);
        split2(buf[cur][2], ah[2], al[2]);
        split2(buf[cur][3], ah[3], al[3]);
#pragma unroll
        for (int nb = 0; nb < 8; nb++) {
            MMA_BF16(acc[nb], ah, bh[nb]);
            MMA_BF16(acc[nb], ah, bl[nb]);
            MMA_BF16(acc[nb], al, bh[nb]);
        }
    }

    // att weights for this lane's columns: ats/atd laid out so index == col
    float ws[8][2], wd[8][2];
#pragma unroll
    for (int nb = 0; nb < 8; nb++) {
        int col = colBase + nb * 8 + tg * 2;
        float2 a = *(const float2*)(ats + col);
        float2 b = *(const float2*)(atd + col);
        ws[nb][0] = a.x; ws[nb][1] = a.y;
        wd[nb][0] = b.x; wd[nb][1] = b.y;
    }

    int gr0 = warpRow + g;
    int gr1 = warpRow + g + 8;
    // emit h16
#pragma unroll
    for (int nb = 0; nb < 8; nb++) {
        int col = colBase + nb * 8 + tg * 2;
        if (gr0 < NN)
            *(__half2*)(g_h16 + (size_t)gr0 * HROW + col) =
                __floats2half2_rn(acc[nb][0], acc[nb][1]);
        if (gr1 < NN)
            *(__half2*)(g_h16 + (size_t)gr1 * HROW + col) =
                __floats2half2_rn(acc[nb][2], acc[nb][3]);
    }
    // fused attention dots: per-head partials, reduced over tg lanes
    float s0[8], d0[8], s1[8], d1[8];
#pragma unroll
    for (int nb = 0; nb < 8; nb++) {
        s0[nb] = acc[nb][0] * ws[nb][0] + acc[nb][1] * ws[nb][1];
        d0[nb] = acc[nb][0] * wd[nb][0] + acc[nb][1] * wd[nb][1];
        s1[nb] = acc[nb][2] * ws[nb][0] + acc[nb][3] * ws[nb][1];
        d1[nb] = acc[nb][2] * wd[nb][0] + acc[nb][3] * wd[nb][1];
    }
    if (CH == 8) {
        // head == nb
#pragma unroll
        for (int nb = 0; nb < 8; nb++) {
#pragma unroll
            for (int dlt = 1; dlt <= 2; dlt <<= 1) {
                s0[nb] += __shfl_xor_sync(0xffffffffu, s0[nb], dlt);
                d0[nb] += __shfl_xor_sync(0xffffffffu, d0[nb], dlt);
                s1[nb] += __shfl_xor_sync(0xffffffffu, s1[nb], dlt);
                d1[nb] += __shfl_xor_sync(0xffffffffu, d1[nb], dlt);
            }
        }
        if (gr0 < NN) {
            g_asrc[gr0 * 8 + tg]     = s0[tg];
            g_asrc[gr0 * 8 + tg + 4] = s0[tg + 4];
            g_adst[gr0 * 8 + tg]     = d0[tg];
            g_adst[gr0 * 8 + tg + 4] = d0[tg + 4];
        }
        if (gr1 < NN) {
            g_asrc[gr1 * 8 + tg]     = s1[tg];
            g_asrc[gr1 * 8 + tg + 4] = s1[tg + 4];
            g_adst[gr1 * 8 + tg]     = d1[tg];
            g_adst[gr1 * 8 + tg + 4] = d1[tg + 4];
        }
    } else {
        // CH == 16: head spans 2 nb; 4 heads per 64-col block
        int headBase = colBase >> 4;
        float hs0[4], hd0[4], hs1[4], hd1[4];
#pragma unroll
        for (int hh = 0; hh < 4; hh++) {
            hs0[hh] = s0[2 * hh] + s0[2 * hh + 1];
            hd0[hh] = d0[2 * hh] + d0[2 * hh + 1];
            hs1[hh] = s1[2 * hh] + s1[2 * hh + 1];
            hd1[hh] = d1[2 * hh] + d1[2 * hh + 1];
#pragma unroll
            for (int dlt = 1; dlt <= 2; dlt <<= 1) {
                hs0[hh] += __shfl_xor_sync(0xffffffffu, hs0[hh], dlt);
                hd0[hh] += __shfl_xor_sync(0xffffffffu, hd0[hh], dlt);
                hs1[hh] += __shfl_xor_sync(0xffffffffu, hs1[hh], dlt);
                hd1[hh] += __shfl_xor_sync(0xffffffffu, hd1[hh], dlt);
            }
        }
        if (gr0 < NN) {
            g_asrc[gr0 * 8 + headBase + tg] = hs0[tg];
            g_adst[gr0 * 8 + headBase + tg] = hd0[tg];
        }
        if (gr1 < NN) {
            g_asrc[gr1 * 8 + headBase + tg] = hs1[tg];
            g_adst[gr1 * 8 + headBase + tg] = hd1[tg];
        }
    }
}

// ---------------------------------------------------------------------------
// Aggregation, ONE-PASS softmax (logits clamped at 70), fp16 h gather.
// One warp per dst node; 2-edge pipeline.
// FINAL: head-mean + bias + log_softmax fused.
// ---------------------------------------------------------------------------
template <int C, bool FINAL>
__global__ __launch_bounds__(256) void k_agg(
    const __half* __restrict__ h16,
    const float* __restrict__ bias,
    const float* __restrict__ prelu_a,
    float* __restrict__ out)
{
    constexpr int VEC = C / 4;
    constexpr int HROW = C * 8;
    int warp = (blockIdx.x * blockDim.x + threadIdx.x) >> 5;
    if (warp >= NN) return;
    int lane = threadIdx.x & 31;
    int head = lane >> 2;

    int beg = g_rowptr[warp];
    int end = g_rowptr[warp + 1];
    float ad = g_adst[warp * 8 + head];

    float ssum = 0.f;
    float acc[VEC];
#pragma unroll
    for (int j = 0; j < VEC; j++) acc[j] = 0.f;

    int i = beg;
    for (; i + 2 <= end; i += 2) {
        int s0 = g_csrc[i];
        int s1 = g_csrc[i + 1];
        float a0 = g_asrc[s0 * 8 + head];
        float a1 = g_asrc[s1 * 8 + head];
        float e0 = a0 + ad; e0 = (e0 < 0.f) ? 0.2f * e0 : e0;
        float e1 = a1 + ad; e1 = (e1 < 0.f) ? 0.2f * e1 : e1;
        float w0 = __expf(fminf(e0, 70.f));
        float w1 = __expf(fminf(e1, 70.f));
        ssum += w0 + w1;
        if (!FINAL) {
            uint32_t u0 = *(const uint32_t*)(h16 + (size_t)s0 * HROW + lane * 2);
            uint32_t u1 = *(const uint32_t*)(h16 + (size_t)s1 * HROW + lane * 2);
            float2 p0 = __half22float2(*(__half2*)&u0);
            float2 p1 = __half22float2(*(__half2*)&u1);
            acc[0] += w0 * p0.x + w1 * p1.x;
            acc[1] += w0 * p0.y + w1 * p1.y;
        } else {
            uint2 u0 = *(const uint2*)(h16 + (size_t)s0 * HROW + lane * 4);
            uint2 u1 = *(const uint2*)(h16 + (size_t)s1 * HROW + lane * 4);
            float2 p00 = __half22float2(*(__half2*)&u0.x);
            float2 p01 = __half22float2(*(__half2*)&u0.y);
            float2 p10 = __half22float2(*(__half2*)&u1.x);
            float2 p11 = __half22float2(*(__half2*)&u1.y);
            acc[0] += w0 * p00.x + w1 * p10.x;
            acc[1] += w0 * p00.y + w1 * p10.y;
            acc[2] += w0 * p01.x + w1 * p11.x;
            acc[3] += w0 * p01.y + w1 * p11.y;
        }
    }
    if (i < end) {
        int s0 = g_csrc[i];
        float a0 = g_asrc[s0 * 8 + head];
        float e0 = a0 + ad; e0 = (e0 < 0.f) ? 0.2f * e0 : e0;
        float w0 = __expf(fminf(e0, 70.f));
        ssum += w0;
        if (!FINAL) {
            uint32_t u0 = *(const uint32_t*)(h16 + (size_t)s0 * HROW + lane * 2);
            float2 p0 = __half22float2(*(__half2*)&u0);
            acc[0] += w0 * p0.x;
            acc[1] += w0 * p0.y;
        } else {
            uint2 u0 = *(const uint2*)(h16 + (size_t)s0 * HROW + lane * 4);
            float2 p00 = __half22float2(*(__half2*)&u0.x);
            float2 p01 = __half22float2(*(__half2*)&u0.y);
            acc[0] += w0 * p00.x;
            acc[1] += w0 * p00.y;
            acc[2] += w0 * p01.x;
            acc[3] += w0 * p01.y;
        }
    }
    float inv = 1.f / (ssum + 1e-16f);

    if (!FINAL) {
        float p = prelu_a[0];
        float v[VEC];
#pragma unroll
        for (int j = 0; j < VEC; j++) {
            float t = acc[j] * inv + bias[lane * VEC + j];
            v[j] = (t >= 0.f) ? t : p * t;
        }
        float2 f = make_float2(v[0], v[1]);
        *(float2*)(out + (size_t)warp * 64 + lane * 2) = f;
    } else {
        // mean over heads (lanes stride 4), + bias, log_softmax over 16 ch
        float v[4];
#pragma unroll
        for (int j = 0; j < 4; j++) v[j] = acc[j] * inv;
#pragma unroll
        for (int j = 0; j < 4; j++) {
            v[j] += __shfl_xor_sync(0xffffffffu, v[j], 4);
            v[j] += __shfl_xor_sync(0xffffffffu, v[j], 8);
            v[j] += __shfl_xor_sync(0xffffffffu, v[j], 16);
            v[j] = v[j] * 0.125f + bias[(lane & 3) * 4 + j];
        }
        float mx = fmaxf(fmaxf(v[0], v[1]), fmaxf(v[2], v[3]));
        mx = fmaxf(mx, __shfl_xor_sync(0xffffffffu, mx, 1));
        mx = fmaxf(mx, __shfl_xor_sync(0xffffffffu, mx, 2));
        float se = 0.f;
#pragma unroll
        for (int j = 0; j < 4; j++) se += __expf(v[j] - mx);
        se += __shfl_xor_sync(0xffffffffu, se, 1);
        se += __shfl_xor_sync(0xffffffffu, se, 2);
        float lse = mx + __logf(se);
        if (lane < 4) {
            float4 f = make_float4(v[0] - lse, v[1] - lse, v[2] - lse, v[3] - lse);
            *(float4*)(out + (size_t)warp * 16 + lane * 4) = f;
        }
    }
}

// ---------------------------------------------------------------------------
// Launch
// ---------------------------------------------------------------------------
extern "C" void kernel_launch(void* const* d_in, const int* in_sizes, int n_in,
                              void* d_out, int out_size)
{
    const float* x   = (const float*)d_in[0];
    const int*   ei  = (const int*)d_in[1];
    const float* W1  = (const float*)d_in[2];
    const float* as1 = (const float*)d_in[3];
    const float* ad1 = (const float*)d_in[4];
    const float* b1  = (const float*)d_in[5];
    const float* W2  = (const float*)d_in[6];
    const float* as2 = (const float*)d_in[7];
    const float* ad2 = (const float*)d_in[8];
    const float* b2  = (const float*)d_in[9];
    const float* W3  = (const float*)d_in[10];
    const float* as3 = (const float*)d_in[11];
    const float* ad3 = (const float*)d_in[12];
    const float* b3  = (const float*)d_in[13];
    const float* p1  = (const float*)d_in[14];
    const float* p2  = (const float*)d_in[15];
    float* out = (float*)d_out;

    void *po, *ph16;
    void *pwh1, *pwl1, *pwh2, *pwl2, *pwh3, *pwl3;
    cudaGetSymbolAddress(&po, g_out);
    cudaGetSymbolAddress(&ph16, g_h16);
    cudaGetSymbolAddress(&pwh1, g_wh1);
    cudaGetSymbolAddress(&pwl1, g_wl1);
    cudaGetSymbolAddress(&pwh2, g_wh2);
    cudaGetSymbolAddress(&pwl2, g_wl2);
    cudaGetSymbolAddress(&pwh3, g_wh3);
    cudaGetSymbolAddress(&pwl3, g_wl3);
    float* o = (float*)po;
    const __half* h16 = (const __half*)ph16;

    const int* esrc = ei;
    const int* edst = ei + NE;

    int agg_blocks = (NN * 32 + 255) / 256;
    dim3 gg1((NN + 63) / 64, 1);   // 1563 CTAs of 128 threads
    dim3 gg3((NN + 63) / 64, 2);

    // Launch order puts gemm1 at position 4 (ncu -s 5 -c 1 capture window).
    k_deg_init<<<(NN + 255) / 256, 256>>>();                              // 1
    k_hist<<<(NE + 255) / 256, 256>>>(edst);                              // 2
    k_wt<<<(64 * 256 + 64 * 320 + 128 * 64 + 255) / 256, 256>>>(W1, W2, W3); // 3

    // Layer-1 GEMM (independent of CSR)
    k_gemm_mma<8, 64><<<gg1, 128>>>(x, 256, (const float*)0, 0,           // 4
                                    (const __nv_bfloat16*)pwh1,
                                    (const __nv_bfloat16*)pwl1, as1, ad1);

    // CSR scan + scatter (coalesced two-level scan)
    k_scan_a<<<SCAN_TILES, SCAN_T>>>();                                   // 5
    k_scan_b<<<1, 256>>>();                                               // 6
    k_scan_c<<<SCAN_TILES, SCAN_T>>>();                                   // 7
    k_scatter<<<(NN + NE + 255) / 256, 256>>>(esrc, edst);                // 8

    // Layer 1 aggregate ; +b1 ; PReLU(p1)
    k_agg<8, false><<<agg_blocks, 256>>>(h16, b1, p1, o);                 // 9

    // Layer 2
    k_gemm_mma<8, 64><<<gg1, 128>>>(x, 256, o, 64,
                                    (const __nv_bfloat16*)pwh2,
                                    (const __nv_bfloat16*)pwl2, as2, ad2);
    k_agg<8, false><<<agg_blocks, 256>>>(h16, b2, p2, o);

    // Layer 3
    k_gemm_mma<16, 128><<<gg3, 128>>>(o, 64, (const float*)0, 0,
                                      (const __nv_bfloat16*)pwh3,
                                      (const __nv_bfloat16*)pwl3, as3, ad3);
    k_agg<16, true><<<agg_blocks, 256>>>(h16, b3, (const float*)0, out);
}

// round 11
// speedup vs baseline: 1.2021x; 1.2021x over previous
#include <cuda_runtime.h>
#include <cuda_fp16.h>
#include <cuda_bf16.h>
#include <stdint.h>

// Problem constants
#define NN 100000
#define NE 1600000
#define NE2 (NE + NN)
#define SCAN_T 512
#define SCAN_TILES ((NN + SCAN_T - 1) / SCAN_T)  // 196

// ---------------------------------------------------------------------------
// Scratch (device globals — no allocation allowed)
// ---------------------------------------------------------------------------
__device__ __half g_h16[(size_t)NN * 128]; // fp16 linear output (all layers)
__device__ float  g_out[(size_t)NN * 64];  // per-layer aggregated output
__device__ float  g_asrc[NN * 8];
__device__ float  g_adst[NN * 8];
__device__ int    g_rowptr[NN + 1];
__device__ int    g_cursor[NN];
__device__ int    g_csrc[NE2];
__device__ int    g_cnt[NN];
__device__ int    g_tilesum[SCAN_TILES];
__device__ int    g_tileoff[SCAN_TILES];
// Weight transposes, bf16 hi/lo split, layout [n][k]
__device__ __nv_bfloat16 g_wh1[64 * 256], g_wl1[64 * 256];
__device__ __nv_bfloat16 g_wh2[64 * 320], g_wl2[64 * 320];
__device__ __nv_bfloat16 g_wh3[128 * 64], g_wl3[128 * 64];

// ---------------------------------------------------------------------------
// CSR build (dst-sorted adjacency incl. self-loops), reused for all 3 layers
// ---------------------------------------------------------------------------
__global__ void k_deg_init() {
    int i = blockIdx.x * blockDim.x + threadIdx.x;
    if (i < NN) g_cnt[i] = 1;  // self loop
}

__global__ void k_hist(const int* __restrict__ edst) {
    int e = blockIdx.x * blockDim.x + threadIdx.x;
    if (e < NE) atomicAdd(&g_cnt[edst[e]], 1);
}

// Coalesced two-level scan: tile reduce -> scan tile sums -> tile-local scan
__global__ __launch_bounds__(SCAN_T) void k_scan_a() {
    __shared__ int sm[SCAN_T];
    int i = blockIdx.x * SCAN_T + threadIdx.x;
    sm[threadIdx.x] = (i < NN) ? g_cnt[i] : 0;
    __syncthreads();
#pragma unroll
    for (int off = SCAN_T / 2; off > 0; off >>= 1) {
        if (threadIdx.x < off) sm[threadIdx.x] += sm[threadIdx.x + off];
        __syncthreads();
    }
    if (threadIdx.x == 0) g_tilesum[blockIdx.x] = sm[0];
}

__global__ __launch_bounds__(256) void k_scan_b() {
    __shared__ int sm[256];
    int t = threadIdx.x;
    int v = (t < SCAN_TILES) ? g_tilesum[t] : 0;
    sm[t] = v;
    __syncthreads();
#pragma unroll
    for (int off = 1; off < 256; off <<= 1) {
        int u = (t >= off) ? sm[t - off] : 0;
        __syncthreads();
        sm[t] += u;
        __syncthreads();
    }
    if (t < SCAN_TILES) g_tileoff[t] = sm[t] - v;  // exclusive prefix of tiles
    if (t == 255) g_rowptr[NN] = sm[255];
}

__global__ __launch_bounds__(SCAN_T) void k_scan_c() {
    __shared__ int sm[SCAN_T];
    int i = blockIdx.x * SCAN_T + threadIdx.x;
    int v = (i < NN) ? g_cnt[i] : 0;
    sm[threadIdx.x] = v;
    __syncthreads();
#pragma unroll
    for (int off = 1; off < SCAN_T; off <<= 1) {
        int u = (threadIdx.x >= off) ? sm[threadIdx.x - off] : 0;
        __syncthreads();
        sm[threadIdx.x] += u;
        __syncthreads();
    }
    if (i < NN) {
        int ex = g_tileoff[blockIdx.x] + sm[threadIdx.x] - v;  // exclusive
        g_rowptr[i] = ex;
        g_cursor[i] = ex;
    }
}

__global__ void k_scatter(const int* __restrict__ esrc, const int* __restrict__ edst) {
    int i = blockIdx.x * blockDim.x + threadIdx.x;
    if (i < NN) {
        int p = atomicAdd(&g_cursor[i], 1);
        g_csrc[p] = i;  // self loop
    } else if (i < NN + NE) {
        int e = i - NN;
        int d = edst[e];
        int p = atomicAdd(&g_cursor[d], 1);
        g_csrc[p] = esrc[e];
    }
}

// ---------------------------------------------------------------------------
// Weight transpose + bf16 hi/lo split: Wt[n][k] = W[k][n]
// ---------------------------------------------------------------------------
__device__ __forceinline__ void wsplit(float w, __nv_bfloat16* ph, __nv_bfloat16* pl) {
    uint32_t u = __float_as_uint(w);
    float hif = __uint_as_float(u & 0xffff0000u);
    *ph = __ushort_as_bfloat16((unsigned short)(u >> 16));
    *pl = __float2bfloat16(w - hif);
}

__global__ void k_wt(const float* __restrict__ W1, const float* __restrict__ W2,
                     const float* __restrict__ W3) {
    int i = blockIdx.x * blockDim.x + threadIdx.x;
    if (i < 64 * 256) {
        int n = i / 256, k = i % 256;
        wsplit(W1[k * 64 + n], &g_wh1[i], &g_wl1[i]);
    } else if (i < 64 * 256 + 64 * 320) {
        int j = i - 64 * 256;
        int n = j / 320, k = j % 320;
        wsplit(W2[k * 64 + n], &g_wh2[j], &g_wl2[j]);
    } else if (i < 64 * 256 + 64 * 320 + 128 * 64) {
        int j = i - 64 * 256 - 64 * 320;
        int n = j / 64, k = j % 64;
        wsplit(W3[k * 128 + n], &g_wh3[j], &g_wl3[j]);
    }
}

// ---------------------------------------------------------------------------
// mma.sync bf16 GEMM, 3-term split, M=32/warp (2 m-tiles), 256-thr CTA,
// depth-1 register double-buffered A prefetch.
// Output: h16 (fp16) + fused attention dots a_src/a_dst (fp32 from accs).
// ---------------------------------------------------------------------------
#define MMA_BF16(c, a, b)                                                     \
    asm volatile(                                                             \
        "mma.sync.aligned.m16n8k16.row.col.f32.bf16.bf16.f32 "                \
        "{%0,%1,%2,%3}, {%4,%5,%6,%7}, {%8,%9}, {%0,%1,%2,%3};"               \
        : "+f"((c)[0]), "+f"((c)[1]), "+f"((c)[2]), "+f"((c)[3])              \
        : "r"((a)[0]), "r"((a)[1]), "r"((a)[2]), "r"((a)[3]),                 \
          "r"((b)[0]), "r"((b)[1]))

__device__ __forceinline__ void split2(float2 f, uint32_t& hi, uint32_t& lo) {
    uint32_t u0 = __float_as_uint(f.x), u1 = __float_as_uint(f.y);
    hi = (u0 >> 16) | (u1 & 0xffff0000u);  // packed bf16x2 (truncated)
    float l0 = f.x - __uint_as_float(u0 & 0xffff0000u);
    float l1 = f.y - __uint_as_float(u1 & 0xffff0000u);
    __nv_bfloat162 lb = __floats2bfloat162_rn(l0, l1);
    lo = *reinterpret_cast<uint32_t*>(&lb);
}

template <int CH, int HROW>
__global__ __launch_bounds__(256) void k_gemm_mma(
    const float* __restrict__ A1, int K1,
    const float* __restrict__ A2, int K2,
    const __nv_bfloat16* __restrict__ Wh,
    const __nv_bfloat16* __restrict__ Wl,
    const float* __restrict__ ats,
    const float* __restrict__ atd)
{
    int tid = threadIdx.x;
    int wid = tid >> 5, lane = tid & 31;
    int g = lane >> 2, tg = lane & 3;
    int warpRow = blockIdx.x * 256 + wid * 32;
    int colBase = blockIdx.y * 64;
    int Ktot = K1 + K2;
    int nch = Ktot >> 4;

    // clamped rows for the 2 m-tiles
    int R0[2], R1[2];
#pragma unroll
    for (int mt = 0; mt < 2; mt++) {
        int r0 = warpRow + mt * 16 + g;
        int r1 = r0 + 8;
        R0[mt] = (r0 >= NN) ? NN - 1 : r0;
        R1[mt] = (r1 >= NN) ? NN - 1 : r1;
    }

    float acc[2][8][4];
#pragma unroll
    for (int mt = 0; mt < 2; mt++)
#pragma unroll
        for (int nb = 0; nb < 8; nb++)
#pragma unroll
            for (int j = 0; j < 4; j++) acc[mt][nb][j] = 0.f;

    // A prefetch buffers: [stage][mt*4 + frag]
    float2 buf[2][8];
    auto issueA = [&](int c, float2* b) {
        int kbase = c << 4;
        const float* src; int stride, koff;
        if (kbase < K1) { src = A1; stride = K1; koff = kbase; }
        else            { src = A2; stride = K2; koff = kbase - K1; }
#pragma unroll
        for (int mt = 0; mt < 2; mt++) {
            const float* p0 = src + (size_t)R0[mt] * stride + koff + tg * 2;
            const float* p1 = src + (size_t)R1[mt] * stride + koff + tg * 2;
            b[mt * 4 + 0] = *(const float2*)p0;
            b[mt * 4 + 1] = *(const float2*)p1;
            b[mt * 4 + 2] = *(const float2*)(p0 + 8);
            b[mt * 4 + 3] = *(const float2*)(p1 + 8);
        }
    };

    issueA(0, buf[0]);
    for (int c = 0; c < nch; c++) {
        int cur = c & 1;
        if (c + 1 < nch) issueA(c + 1, buf[cur ^ 1]);

        int kbase = c << 4;
        uint32_t bh[8][2], bl[8][2];
#pragma unroll
        for (int nb = 0; nb < 8; nb++) {
            int n = colBase + nb * 8 + g;
            size_t base = (size_t)n * Ktot + kbase + tg * 2;
            bh[nb][0] = *(const uint32_t*)(Wh + base);
            bh[nb][1] = *(const uint32_t*)(Wh + base + 8);
            bl[nb][0] = *(const uint32_t*)(Wl + base);
            bl[nb][1] = *(const uint32_t*)(Wl + base + 8);
        }

#pragma unroll
        for (int mt = 0; mt < 2; mt++) {
            uint32_t ah[4], al[4];
            split2(buf[cur][mt * 4 + 0], ah[0], al[0]);
            split2(buf[cur][mt * 4 + 1], ah[1], al[1]);
            split2(buf[cur][mt * 4 + 2], ah[2], al[2]);
            split2(buf[cur][mt * 4 + 3], ah[3], al[3]);
#pragma unroll
            for (int nb = 0; nb < 8; nb++) {
                MMA_BF16(acc[mt][nb], ah, bh[nb]);
                MMA_BF16(acc[mt][nb], ah, bl[nb]);
                MMA_BF16(acc[mt][nb], al, bh[nb]);
            }
        }
    }

    // att weights for this lane's columns: ats/atd laid out so index == col
    float ws[8][2], wd[8][2];
#pragma unroll
    for (int nb = 0; nb < 8; nb++) {
        int col = colBase + nb * 8 + tg * 2;
        float2 a = *(const float2*)(ats + col);
        float2 b = *(const float2*)(atd + col);
        ws[nb][0] = a.x; ws[nb][1] = a.y;
        wd[nb][0] = b.x; wd[nb][1] = b.y;
    }

#pragma unroll
    for (int mt = 0; mt < 2; mt++) {
        int r0 = warpRow + mt * 16 + g;
        int r1 = r0 + 8;
        // emit h16
#pragma unroll
        for (int nb = 0; nb < 8; nb++) {
            int col = colBase + nb * 8 + tg * 2;
            if (r0 < NN)
                *(__half2*)(g_h16 + (size_t)r0 * HROW + col) =
                    __floats2half2_rn(acc[mt][nb][0], acc[mt][nb][1]);
            if (r1 < NN)
                *(__half2*)(g_h16 + (size_t)r1 * HROW + col) =
                    __floats2half2_rn(acc[mt][nb][2], acc[mt][nb][3]);
        }
        // fused attention dots: per-head partials, reduced over tg lanes
        float s0[8], d0[8], s1[8], d1[8];
#pragma unroll
        for (int nb = 0; nb < 8; nb++) {
            s0[nb] = acc[mt][nb][0] * ws[nb][0] + acc[mt][nb][1] * ws[nb][1];
            d0[nb] = acc[mt][nb][0] * wd[nb][0] + acc[mt][nb][1] * wd[nb][1];
            s1[nb] = acc[mt][nb][2] * ws[nb][0] + acc[mt][nb][3] * ws[nb][1];
            d1[nb] = acc[mt][nb][2] * wd[nb][0] + acc[mt][nb][3] * wd[nb][1];
        }
        if (CH == 8) {
            // head == nb
#pragma unroll
            for (int nb = 0; nb < 8; nb++) {
#pragma unroll
                for (int dlt = 1; dlt <= 2; dlt <<= 1) {
                    s0[nb] += __shfl_xor_sync(0xffffffffu, s0[nb], dlt);
                    d0[nb] += __shfl_xor_sync(0xffffffffu, d0[nb], dlt);
                    s1[nb] += __shfl_xor_sync(0xffffffffu, s1[nb], dlt);
                    d1[nb] += __shfl_xor_sync(0xffffffffu, d1[nb], dlt);
                }
            }
            if (r0 < NN) {
                g_asrc[r0 * 8 + tg]     = s0[tg];
                g_asrc[r0 * 8 + tg + 4] = s0[tg + 4];
                g_adst[r0 * 8 + tg]     = d0[tg];
                g_adst[r0 * 8 + tg + 4] = d0[tg + 4];
            }
            if (r1 < NN) {
                g_asrc[r1 * 8 + tg]     = s1[tg];
                g_asrc[r1 * 8 + tg + 4] = s1[tg + 4];
                g_adst[r1 * 8 + tg]     = d1[tg];
                g_adst[r1 * 8 + tg + 4] = d1[tg + 4];
            }
        } else {
            // CH == 16: head spans 2 nb; 4 heads per 64-col block
            int headBase = colBase >> 4;
            float hs0[4], hd0[4], hs1[4], hd1[4];
#pragma unroll
            for (int hh = 0; hh < 4; hh++) {
                hs0[hh] = s0[2 * hh] + s0[2 * hh + 1];
                hd0[hh] = d0[2 * hh] + d0[2 * hh + 1];
                hs1[hh] = s1[2 * hh] + s1[2 * hh + 1];
                hd1[hh] = d1[2 * hh] + d1[2 * hh + 1];
#pragma unroll
                for (int dlt = 1; dlt <= 2; dlt <<= 1) {
                    hs0[hh] += __shfl_xor_sync(0xffffffffu, hs0[hh], dlt);
                    hd0[hh] += __shfl_xor_sync(0xffffffffu, hd0[hh], dlt);
                    hs1[hh] += __shfl_xor_sync(0xffffffffu, hs1[hh], dlt);
                    hd1[hh] += __shfl_xor_sync(0xffffffffu, hd1[hh], dlt);
                }
            }
            if (r0 < NN) {
                g_asrc[r0 * 8 + headBase + tg] = hs0[tg];
                g_adst[r0 * 8 + headBase + tg] = hd0[tg];
            }
            if (r1 < NN) {
                g_asrc[r1 * 8 + headBase + tg] = hs1[tg];
                g_adst[r1 * 8 + headBase + tg] = hd1[tg];
            }
        }
    }
}

// ---------------------------------------------------------------------------
// Aggregation, ONE-PASS softmax (logits clamped at 70), fp16 h gather.
// One warp per dst node; 2-edge pipeline.
// FINAL: head-mean + bias + log_softmax fused.
// ---------------------------------------------------------------------------
template <int C, bool FINAL>
__global__ __launch_bounds__(256) void k_agg(
    const __half* __restrict__ h16,
    const float* __restrict__ bias,
    const float* __restrict__ prelu_a,
    float* __restrict__ out)
{
    constexpr int VEC = C / 4;
    constexpr int HROW = C * 8;
    int warp = (blockIdx.x * blockDim.x + threadIdx.x) >> 5;
    if (warp >= NN) return;
    int lane = threadIdx.x & 31;
    int head = lane >> 2;

    int beg = g_rowptr[warp];
    int end = g_rowptr[warp + 1];
    float ad = g_adst[warp * 8 + head];

    float ssum = 0.f;
    float acc[VEC];
#pragma unroll
    for (int j = 0; j < VEC; j++) acc[j] = 0.f;

    int i = beg;
    for (; i + 2 <= end; i += 2) {
        int s0 = g_csrc[i];
        int s1 = g_csrc[i + 1];
        float a0 = g_asrc[s0 * 8 + head];
        float a1 = g_asrc[s1 * 8 + head];
        float e0 = a0 + ad; e0 = (e0 < 0.f) ? 0.2f * e0 : e0;
        float e1 = a1 + ad; e1 = (e1 < 0.f) ? 0.2f * e1 : e1;
        float w0 = __expf(fminf(e0, 70.f));
        float w1 = __expf(fminf(e1, 70.f));
        ssum += w0 + w1;
        if (!FINAL) {
            uint32_t u0 = *(const uint32_t*)(h16 + (size_t)s0 * HROW + lane * 2);
            uint32_t u1 = *(const uint32_t*)(h16 + (size_t)s1 * HROW + lane * 2);
            float2 p0 = __half22float2(*(__half2*)&u0);
            float2 p1 = __half22float2(*(__half2*)&u1);
            acc[0] += w0 * p0.x + w1 * p1.x;
            acc[1] += w0 * p0.y + w1 * p1.y;
        } else {
            uint2 u0 = *(const uint2*)(h16 + (size_t)s0 * HROW + lane * 4);
            uint2 u1 = *(const uint2*)(h16 + (size_t)s1 * HROW + lane * 4);
            float2 p00 = __half22float2(*(__half2*)&u0.x);
            float2 p01 = __half22float2(*(__half2*)&u0.y);
            float2 p10 = __half22float2(*(__half2*)&u1.x);
            float2 p11 = __half22float2(*(__half2*)&u1.y);
            acc[0] += w0 * p00.x + w1 * p10.x;
            acc[1] += w0 * p00.y + w1 * p10.y;
            acc[2] += w0 * p01.x + w1 * p11.x;
            acc[3] += w0 * p01.y + w1 * p11.y;
        }
    }
    if (i < end) {
        int s0 = g_csrc[i];
        float a0 = g_asrc[s0 * 8 + head];
        float e0 = a0 + ad; e0 = (e0 < 0.f) ? 0.2f * e0 : e0;
        float w0 = __expf(fminf(e0, 70.f));
        ssum += w0;
        if (!FINAL) {
            uint32_t u0 = *(const uint32_t*)(h16 + (size_t)s0 * HROW + lane * 2);
            float2 p0 = __half22float2(*(__half2*)&u0);
            acc[0] += w0 * p0.x;
            acc[1] += w0 * p0.y;
        } else {
            uint2 u0 = *(const uint2*)(h16 + (size_t)s0 * HROW + lane * 4);
            float2 p00 = __half22float2(*(__half2*)&u0.x);
            float2 p01 = __half22float2(*(__half2*)&u0.y);
            acc[0] += w0 * p00.x;
            acc[1] += w0 * p00.y;
            acc[2] += w0 * p01.x;
            acc[3] += w0 * p01.y;
        }
    }
    float inv = 1.f / (ssum + 1e-16f);

    if (!FINAL) {
        float p = prelu_a[0];
        float v[VEC];
#pragma unroll
        for (int j = 0; j < VEC; j++) {
            float t = acc[j] * inv + bias[lane * VEC + j];
            v[j] = (t >= 0.f) ? t : p * t;
        }
        float2 f = make_float2(v[0], v[1]);
        *(float2*)(out + (size_t)warp * 64 + lane * 2) = f;
    } else {
        // mean over heads (lanes stride 4), + bias, log_softmax over 16 ch
        float v[4];
#pragma unroll
        for (int j = 0; j < 4; j++) v[j] = acc[j] * inv;
#pragma unroll
        for (int j = 0; j < 4; j++) {
            v[j] += __shfl_xor_sync(0xffffffffu, v[j], 4);
            v[j] += __shfl_xor_sync(0xffffffffu, v[j], 8);
            v[j] += __shfl_xor_sync(0xffffffffu, v[j], 16);
            v[j] = v[j] * 0.125f + bias[(lane & 3) * 4 + j];
        }
        float mx = fmaxf(fmaxf(v[0], v[1]), fmaxf(v[2], v[3]));
        mx = fmaxf(mx, __shfl_xor_sync(0xffffffffu, mx, 1));
        mx = fmaxf(mx, __shfl_xor_sync(0xffffffffu, mx, 2));
        float se = 0.f;
#pragma unroll
        for (int j = 0; j < 4; j++) se += __expf(v[j] - mx);
        se += __shfl_xor_sync(0xffffffffu, se, 1);
        se += __shfl_xor_sync(0xffffffffu, se, 2);
        float lse = mx + __logf(se);
        if (lane < 4) {
            float4 f = make_float4(v[0] - lse, v[1] - lse, v[2] - lse, v[3] - lse);
            *(float4*)(out + (size_t)warp * 16 + lane * 4) = f;
        }
    }
}

// ---------------------------------------------------------------------------
// Launch
// ---------------------------------------------------------------------------
extern "C" void kernel_launch(void* const* d_in, const int* in_sizes, int n_in,
                              void* d_out, int out_size)
{
    const float* x   = (const float*)d_in[0];
    const int*   ei  = (const int*)d_in[1];
    const float* W1  = (const float*)d_in[2];
    const float* as1 = (const float*)d_in[3];
    const float* ad1 = (const float*)d_in[4];
    const float* b1  = (const float*)d_in[5];
    const float* W2  = (const float*)d_in[6];
    const float* as2 = (const float*)d_in[7];
    const float* ad2 = (const float*)d_in[8];
    const float* b2  = (const float*)d_in[9];
    const float* W3  = (const float*)d_in[10];
    const float* as3 = (const float*)d_in[11];
    const float* ad3 = (const float*)d_in[12];
    const float* b3  = (const float*)d_in[13];
    const float* p1  = (const float*)d_in[14];
    const float* p2  = (const float*)d_in[15];
    float* out = (float*)d_out;

    void *po, *ph16;
    void *pwh1, *pwl1, *pwh2, *pwl2, *pwh3, *pwl3;
    cudaGetSymbolAddress(&po, g_out);
    cudaGetSymbolAddress(&ph16, g_h16);
    cudaGetSymbolAddress(&pwh1, g_wh1);
    cudaGetSymbolAddress(&pwl1, g_wl1);
    cudaGetSymbolAddress(&pwh2, g_wh2);
    cudaGetSymbolAddress(&pwl2, g_wl2);
    cudaGetSymbolAddress(&pwh3, g_wh3);
    cudaGetSymbolAddress(&pwl3, g_wl3);
    float* o = (float*)po;
    const __half* h16 = (const __half*)ph16;

    const int* esrc = ei;
    const int* edst = ei + NE;

    int agg_blocks = (NN * 32 + 255) / 256;
    dim3 gg1((NN + 255) / 256, 1);   // 391 CTAs of 256 threads
    dim3 gg3((NN + 255) / 256, 2);

    // Launch order puts gemm1 at position 4 (ncu -s 5 -c 1 capture window).
    k_deg_init<<<(NN + 255) / 256, 256>>>();                              // 1
    k_hist<<<(NE + 255) / 256, 256>>>(edst);                              // 2
    k_wt<<<(64 * 256 + 64 * 320 + 128 * 64 + 255) / 256, 256>>>(W1, W2, W3); // 3

    // Layer-1 GEMM (independent of CSR)
    k_gemm_mma<8, 64><<<gg1, 256>>>(x, 256, (const float*)0, 0,           // 4
                                    (const __nv_bfloat16*)pwh1,
                                    (const __nv_bfloat16*)pwl1, as1, ad1);

    // CSR scan + scatter (coalesced two-level scan)
    k_scan_a<<<SCAN_TILES, SCAN_T>>>();                                   // 5
    k_scan_b<<<1, 256>>>();                                               // 6
    k_scan_c<<<SCAN_TILES, SCAN_T>>>();                                   // 7
    k_scatter<<<(NN + NE + 255) / 256, 256>>>(esrc, edst);                // 8

    // Layer 1 aggregate ; +b1 ; PReLU(p1)
    k_agg<8, false><<<agg_blocks, 256>>>(h16, b1, p1, o);                 // 9

    // Layer 2
    k_gemm_mma<8, 64><<<gg1, 256>>>(x, 256, o, 64,
                                    (const __nv_bfloat16*)pwh2,
                                    (const __nv_bfloat16*)pwl2, as2, ad2);
    k_agg<8, false><<<agg_blocks, 256>>>(h16, b2, p2, o);

    // Layer 3
    k_gemm_mma<16, 128><<<gg3, 256>>>(o, 64, (const float*)0, 0,
                                      (const __nv_bfloat16*)pwh3,
                                      (const __nv_bfloat16*)pwl3, as3, ad3);
    k_agg<16, true><<<agg_blocks, 256>>>(h16, b3, (const float*)0, out);
}

// round 12
// speedup vs baseline: 1.2745x; 1.0602x over previous
#include <cuda_runtime.h>
#include <cuda_fp16.h>
#include <cuda_bf16.h>
#include <stdint.h>

// Problem constants
#define NN 100000
#define NE 1600000
#define NE2 (NE + NN)
#define SCAN_T 512
#define SCAN_TILES ((NN + SCAN_T - 1) / SCAN_T)  // 196

// GEMM A-pipeline
#define STAGES 4
#define ROWPAD 20                    // floats per row in smem (16 + 4 pad)
#define STAGE_F (256 * ROWPAD)       // floats per stage
#define GEMM_SMEM (STAGES * STAGE_F * 4)  // 81920 bytes

// ---------------------------------------------------------------------------
// Scratch (device globals — no allocation allowed)
// ---------------------------------------------------------------------------
__device__ __half g_h16[(size_t)NN * 128]; // fp16 linear output (all layers)
__device__ float  g_out[(size_t)NN * 64];  // per-layer aggregated output
__device__ float  g_asrc[NN * 8];
__device__ float  g_adst[NN * 8];
__device__ int    g_rowptr[NN + 1];
__device__ int    g_cursor[NN];
__device__ int    g_csrc[NE2];
__device__ int    g_cnt[NN];
__device__ int    g_tilesum[SCAN_TILES];
__device__ int    g_tileoff[SCAN_TILES];
// Weight transposes, bf16 hi/lo split, layout [n][k]
__device__ __nv_bfloat16 g_wh1[64 * 256], g_wl1[64 * 256];
__device__ __nv_bfloat16 g_wh2[64 * 320], g_wl2[64 * 320];
__device__ __nv_bfloat16 g_wh3[128 * 64], g_wl3[128 * 64];

// ---------------------------------------------------------------------------
// CSR build (dst-sorted adjacency incl. self-loops), reused for all 3 layers
// ---------------------------------------------------------------------------
__global__ void k_deg_init() {
    int i = blockIdx.x * blockDim.x + threadIdx.x;
    if (i < NN) g_cnt[i] = 1;  // self loop
}

__global__ void k_hist(const int* __restrict__ edst) {
    int e = blockIdx.x * blockDim.x + threadIdx.x;
    if (e < NE) atomicAdd(&g_cnt[edst[e]], 1);
}

// Coalesced two-level scan: tile reduce -> scan tile sums -> tile-local scan
__global__ __launch_bounds__(SCAN_T) void k_scan_a() {
    __shared__ int sm[SCAN_T];
    int i = blockIdx.x * SCAN_T + threadIdx.x;
    sm[threadIdx.x] = (i < NN) ? g_cnt[i] : 0;
    __syncthreads();
#pragma unroll
    for (int off = SCAN_T / 2; off > 0; off >>= 1) {
        if (threadIdx.x < off) sm[threadIdx.x] += sm[threadIdx.x + off];
        __syncthreads();
    }
    if (threadIdx.x == 0) g_tilesum[blockIdx.x] = sm[0];
}

__global__ __launch_bounds__(256) void k_scan_b() {
    __shared__ int sm[256];
    int t = threadIdx.x;
    int v = (t < SCAN_TILES) ? g_tilesum[t] : 0;
    sm[t] = v;
    __syncthreads();
#pragma unroll
    for (int off = 1; off < 256; off <<= 1) {
        int u = (t >= off) ? sm[t - off] : 0;
        __syncthreads();
        sm[t] += u;
        __syncthreads();
    }
    if (t < SCAN_TILES) g_tileoff[t] = sm[t] - v;  // exclusive prefix of tiles
    if (t == 255) g_rowptr[NN] = sm[255];
}

__global__ __launch_bounds__(SCAN_T) void k_scan_c() {
    __shared__ int sm[SCAN_T];
    int i = blockIdx.x * SCAN_T + threadIdx.x;
    int v = (i < NN) ? g_cnt[i] : 0;
    sm[threadIdx.x] = v;
    __syncthreads();
#pragma unroll
    for (int off = 1; off < SCAN_T; off <<= 1) {
        int u = (threadIdx.x >= off) ? sm[threadIdx.x - off] : 0;
        __syncthreads();
        sm[threadIdx.x] += u;
        __syncthreads();
    }
    if (i < NN) {
        int ex = g_tileoff[blockIdx.x] + sm[threadIdx.x] - v;  // exclusive
        g_rowptr[i] = ex;
        g_cursor[i] = ex;
    }
}

__global__ void k_scatter(const int* __restrict__ esrc, const int* __restrict__ edst) {
    int i = blockIdx.x * blockDim.x + threadIdx.x;
    if (i < NN) {
        int p = atomicAdd(&g_cursor[i], 1);
        g_csrc[p] = i;  // self loop
    } else if (i < NN + NE) {
        int e = i - NN;
        int d = edst[e];
        int p = atomicAdd(&g_cursor[d], 1);
        g_csrc[p] = esrc[e];
    }
}

// ---------------------------------------------------------------------------
// Weight transpose + bf16 hi/lo split: Wt[n][k] = W[k][n]
// ---------------------------------------------------------------------------
__device__ __forceinline__ void wsplit(float w, __nv_bfloat16* ph, __nv_bfloat16* pl) {
    uint32_t u = __float_as_uint(w);
    float hif = __uint_as_float(u & 0xffff0000u);
    *ph = __ushort_as_bfloat16((unsigned short)(u >> 16));
    *pl = __float2bfloat16(w - hif);
}

__global__ void k_wt(const float* __restrict__ W1, const float* __restrict__ W2,
                     const float* __restrict__ W3) {
    int i = blockIdx.x * blockDim.x + threadIdx.x;
    if (i < 64 * 256) {
        int n = i / 256, k = i % 256;
        wsplit(W1[k * 64 + n], &g_wh1[i], &g_wl1[i]);
    } else if (i < 64 * 256 + 64 * 320) {
        int j = i - 64 * 256;
        int n = j / 320, k = j % 320;
        wsplit(W2[k * 64 + n], &g_wh2[j], &g_wl2[j]);
    } else if (i < 64 * 256 + 64 * 320 + 128 * 64) {
        int j = i - 64 * 256 - 64 * 320;
        int n = j / 64, k = j % 64;
        wsplit(W3[k * 128 + n], &g_wh3[j], &g_wl3[j]);
    }
}

// ---------------------------------------------------------------------------
// mma.sync bf16 GEMM, 3-term split, M=32/warp (2 m-tiles), 256-thr CTA.
// A streamed via 4-stage cp.async smem pipeline; B direct LDG (L1-resident).
// Output: h16 (fp16) + fused attention dots a_src/a_dst (fp32 from accs).
// ---------------------------------------------------------------------------
#define MMA_BF16(c, a, b)                                                     \
    asm volatile(                                                             \
        "mma.sync.aligned.m16n8k16.row.col.f32.bf16.bf16.f32 "                \
        "{%0,%1,%2,%3}, {%4,%5,%6,%7}, {%8,%9}, {%0,%1,%2,%3};"               \
        : "+f"((c)[0]), "+f"((c)[1]), "+f"((c)[2]), "+f"((c)[3])              \
        : "r"((a)[0]), "r"((a)[1]), "r"((a)[2]), "r"((a)[3]),                 \
          "r"((b)[0]), "r"((b)[1]))

__device__ __forceinline__ void split2(float2 f, uint32_t& hi, uint32_t& lo) {
    uint32_t u0 = __float_as_uint(f.x), u1 = __float_as_uint(f.y);
    hi = (u0 >> 16) | (u1 & 0xffff0000u);  // packed bf16x2 (truncated)
    float l0 = f.x - __uint_as_float(u0 & 0xffff0000u);
    float l1 = f.y - __uint_as_float(u1 & 0xffff0000u);
    __nv_bfloat162 lb = __floats2bfloat162_rn(l0, l1);
    lo = *reinterpret_cast<uint32_t*>(&lb);
}

template <int CH, int HROW>
__global__ __launch_bounds__(256) void k_gemm_mma(
    const float* __restrict__ A1, int K1,
    const float* __restrict__ A2, int K2,
    const __nv_bfloat16* __restrict__ Wh,
    const __nv_bfloat16* __restrict__ Wl,
    const float* __restrict__ ats,
    const float* __restrict__ atd)
{
    extern __shared__ float sA[];  // STAGES * STAGE_F
    int tid = threadIdx.x;
    int wid = tid >> 5, lane = tid & 31;
    int g = lane >> 2, tg = lane & 3;
    int blockRow = blockIdx.x * 256;
    int warpRow = blockRow + wid * 32;
    int colBase = blockIdx.y * 64;
    int Ktot = K1 + K2;
    int nch = Ktot >> 4;

    float acc[2][8][4];
#pragma unroll
    for (int mt = 0; mt < 2; mt++)
#pragma unroll
        for (int nb = 0; nb < 8; nb++)
#pragma unroll
            for (int j = 0; j < 4; j++) acc[mt][nb][j] = 0.f;

    // cp.async issue of chunk c into stage (c & 3): 4 x 16B per thread
    auto issueA = [&](int c) {
        float* dst = sA + (c & (STAGES - 1)) * STAGE_F;
        int kbase = c << 4;
        const float* src; int stride, koff;
        if (kbase < K1) { src = A1; stride = K1; koff = kbase; }
        else            { src = A2; stride = K2; koff = kbase - K1; }
#pragma unroll
        for (int i = 0; i < 4; i++) {
            int idx = tid + i * 256;          // 0..1023
            int lr = idx >> 2;                // local row 0..255
            int c4 = (idx & 3) * 4;           // float offset 0/4/8/12
            int grow = blockRow + lr; if (grow >= NN) grow = NN - 1;
            const float* gp = src + (size_t)grow * stride + koff + c4;
            uint32_t sa = (uint32_t)__cvta_generic_to_shared(dst + lr * ROWPAD + c4);
            asm volatile("cp.async.cg.shared.global [%0], [%1], 16;"
                         :: "r"(sa), "l"(gp) : "memory");
        }
    };

    // prologue: stages 0..STAGES-2
#pragma unroll
    for (int s = 0; s < STAGES - 1; s++) {
        if (s < nch) issueA(s);
        asm volatile("cp.async.commit_group;" ::: "memory");
    }

    for (int c = 0; c < nch; c++) {
        asm volatile("cp.async.wait_group %0;" :: "n"(STAGES - 2) : "memory");
        __syncthreads();

        int kbase = c << 4;
        uint32_t bh[8][2], bl[8][2];
#pragma unroll
        for (int nb = 0; nb < 8; nb++) {
            int n = colBase + nb * 8 + g;
            size_t base = (size_t)n * Ktot + kbase + tg * 2;
            bh[nb][0] = *(const uint32_t*)(Wh + base);
            bh[nb][1] = *(const uint32_t*)(Wh + base + 8);
            bl[nb][0] = *(const uint32_t*)(Wl + base);
            bl[nb][1] = *(const uint32_t*)(Wl + base + 8);
        }

        const float* st = sA + (c & (STAGES - 1)) * STAGE_F;
#pragma unroll
        for (int mt = 0; mt < 2; mt++) {
            int lr0 = wid * 32 + mt * 16 + g;
            int lr1 = lr0 + 8;
            float2 f0 = *(const float2*)(st + lr0 * ROWPAD + tg * 2);
            float2 f1 = *(const float2*)(st + lr1 * ROWPAD + tg * 2);
            float2 f2 = *(const float2*)(st + lr0 * ROWPAD + 8 + tg * 2);
            float2 f3 = *(const float2*)(st + lr1 * ROWPAD + 8 + tg * 2);
            uint32_t ah[4], al[4];
            split2(f0, ah[0], al[0]);
            split2(f1, ah[1], al[1]);
            split2(f2, ah[2], al[2]);
            split2(f3, ah[3], al[3]);
#pragma unroll
            for (int nb = 0; nb < 8; nb++) {
                MMA_BF16(acc[mt][nb], ah, bh[nb]);
                MMA_BF16(acc[mt][nb], ah, bl[nb]);
                MMA_BF16(acc[mt][nb], al, bh[nb]);
            }
        }

        if (c + STAGES - 1 < nch) issueA(c + STAGES - 1);
        asm volatile("cp.async.commit_group;" ::: "memory");
    }

    // att weights for this lane's columns: ats/atd laid out so index == col
    float ws[8][2], wd[8][2];
#pragma unroll
    for (int nb = 0; nb < 8; nb++) {
        int col = colBase + nb * 8 + tg * 2;
        float2 a = *(const float2*)(ats + col);
        float2 b = *(const float2*)(atd + col);
        ws[nb][0] = a.x; ws[nb][1] = a.y;
        wd[nb][0] = b.x; wd[nb][1] = b.y;
    }

#pragma unroll
    for (int mt = 0; mt < 2; mt++) {
        int r0 = warpRow + mt * 16 + g;
        int r1 = r0 + 8;
        // emit h16
#pragma unroll
        for (int nb = 0; nb < 8; nb++) {
            int col = colBase + nb * 8 + tg * 2;
            if (r0 < NN)
                *(__half2*)(g_h16 + (size_t)r0 * HROW + col) =
                    __floats2half2_rn(acc[mt][nb][0], acc[mt][nb][1]);
            if (r1 < NN)
                *(__half2*)(g_h16 + (size_t)r1 * HROW + col) =
                    __floats2half2_rn(acc[mt][nb][2], acc[mt][nb][3]);
        }
        // fused attention dots: per-head partials, reduced over tg lanes
        float s0[8], d0[8], s1[8], d1[8];
#pragma unroll
        for (int nb = 0; nb < 8; nb++) {
            s0[nb] = acc[mt][nb][0] * ws[nb][0] + acc[mt][nb][1] * ws[nb][1];
            d0[nb] = acc[mt][nb][0] * wd[nb][0] + acc[mt][nb][1] * wd[nb][1];
            s1[nb] = acc[mt][nb][2] * ws[nb][0] + acc[mt][nb][3] * ws[nb][1];
            d1[nb] = acc[mt][nb][2] * wd[nb][0] + acc[mt][nb][3] * wd[nb][1];
        }
        if (CH == 8) {
            // head == nb
#pragma unroll
            for (int nb = 0; nb < 8; nb++) {
#pragma unroll
                for (int dlt = 1; dlt <= 2; dlt <<= 1) {
                    s0[nb] += __shfl_xor_sync(0xffffffffu, s0[nb], dlt);
                    d0[nb] += __shfl_xor_sync(0xffffffffu, d0[nb], dlt);
                    s1[nb] += __shfl_xor_sync(0xffffffffu, s1[nb], dlt);
                    d1[nb] += __shfl_xor_sync(0xffffffffu, d1[nb], dlt);
                }
            }
            if (r0 < NN) {
                g_asrc[r0 * 8 + tg]     = s0[tg];
                g_asrc[r0 * 8 + tg + 4] = s0[tg + 4];
                g_adst[r0 * 8 + tg]     = d0[tg];
                g_adst[r0 * 8 + tg + 4] = d0[tg + 4];
            }
            if (r1 < NN) {
                g_asrc[r1 * 8 + tg]     = s1[tg];
                g_asrc[r1 * 8 + tg + 4] = s1[tg + 4];
                g_adst[r1 * 8 + tg]     = d1[tg];
                g_adst[r1 * 8 + tg + 4] = d1[tg + 4];
            }
        } else {
            // CH == 16: head spans 2 nb; 4 heads per 64-col block
            int headBase = colBase >> 4;
            float hs0[4], hd0[4], hs1[4], hd1[4];
#pragma unroll
            for (int hh = 0; hh < 4; hh++) {
                hs0[hh] = s0[2 * hh] + s0[2 * hh + 1];
                hd0[hh] = d0[2 * hh] + d0[2 * hh + 1];
                hs1[hh] = s1[2 * hh] + s1[2 * hh + 1];
                hd1[hh] = d1[2 * hh] + d1[2 * hh + 1];
#pragma unroll
                for (int dlt = 1; dlt <= 2; dlt <<= 1) {
                    hs0[hh] += __shfl_xor_sync(0xffffffffu, hs0[hh], dlt);
                    hd0[hh] += __shfl_xor_sync(0xffffffffu, hd0[hh], dlt);
                    hs1[hh] += __shfl_xor_sync(0xffffffffu, hs1[hh], dlt);
                    hd1[hh] += __shfl_xor_sync(0xffffffffu, hd1[hh], dlt);
                }
            }
            if (r0 < NN) {
                g_asrc[r0 * 8 + headBase + tg] = hs0[tg];
                g_adst[r0 * 8 + headBase + tg] = hd0[tg];
            }
            if (r1 < NN) {
                g_asrc[r1 * 8 + headBase + tg] = hs1[tg];
                g_adst[r1 * 8 + headBase + tg] = hd1[tg];
            }
        }
    }
}

// ---------------------------------------------------------------------------
// Aggregation, ONE-PASS softmax (logits clamped at 70), fp16 h gather.
// One warp per dst node; 2-edge pipeline.
// FINAL: head-mean + bias + log_softmax fused.
// ---------------------------------------------------------------------------
template <int C, bool FINAL>
__global__ __launch_bounds__(256) void k_agg(
    const __half* __restrict__ h16,
    const float* __restrict__ bias,
    const float* __restrict__ prelu_a,
    float* __restrict__ out)
{
    constexpr int VEC = C / 4;
    constexpr int HROW = C * 8;
    int warp = (blockIdx.x * blockDim.x + threadIdx.x) >> 5;
    if (warp >= NN) return;
    int lane = threadIdx.x & 31;
    int head = lane >> 2;

    int beg = g_rowptr[warp];
    int end = g_rowptr[warp + 1];
    float ad = g_adst[warp * 8 + head];

    float ssum = 0.f;
    float acc[VEC];
#pragma unroll
    for (int j = 0; j < VEC; j++) acc[j] = 0.f;

    int i = beg;
    for (; i + 2 <= end; i += 2) {
        int s0 = g_csrc[i];
        int s1 = g_csrc[i + 1];
        float a0 = g_asrc[s0 * 8 + head];
        float a1 = g_asrc[s1 * 8 + head];
        float e0 = a0 + ad; e0 = (e0 < 0.f) ? 0.2f * e0 : e0;
        float e1 = a1 + ad; e1 = (e1 < 0.f) ? 0.2f * e1 : e1;
        float w0 = __expf(fminf(e0, 70.f));
        float w1 = __expf(fminf(e1, 70.f));
        ssum += w0 + w1;
        if (!FINAL) {
            uint32_t u0 = *(const uint32_t*)(h16 + (size_t)s0 * HROW + lane * 2);
            uint32_t u1 = *(const uint32_t*)(h16 + (size_t)s1 * HROW + lane * 2);
            float2 p0 = __half22float2(*(__half2*)&u0);
            float2 p1 = __half22float2(*(__half2*)&u1);
            acc[0] += w0 * p0.x + w1 * p1.x;
            acc[1] += w0 * p0.y + w1 * p1.y;
        } else {
            uint2 u0 = *(const uint2*)(h16 + (size_t)s0 * HROW + lane * 4);
            uint2 u1 = *(const uint2*)(h16 + (size_t)s1 * HROW + lane * 4);
            float2 p00 = __half22float2(*(__half2*)&u0.x);
            float2 p01 = __half22float2(*(__half2*)&u0.y);
            float2 p10 = __half22float2(*(__half2*)&u1.x);
            float2 p11 = __half22float2(*(__half2*)&u1.y);
            acc[0] += w0 * p00.x + w1 * p10.x;
            acc[1] += w0 * p00.y + w1 * p10.y;
            acc[2] += w0 * p01.x + w1 * p11.x;
            acc[3] += w0 * p01.y + w1 * p11.y;
        }
    }
    if (i < end) {
        int s0 = g_csrc[i];
        float a0 = g_asrc[s0 * 8 + head];
        float e0 = a0 + ad; e0 = (e0 < 0.f) ? 0.2f * e0 : e0;
        float w0 = __expf(fminf(e0, 70.f));
        ssum += w0;
        if (!FINAL) {
            uint32_t u0 = *(const uint32_t*)(h16 + (size_t)s0 * HROW + lane * 2);
            float2 p0 = __half22float2(*(__half2*)&u0);
            acc[0] += w0 * p0.x;
            acc[1] += w0 * p0.y;
        } else {
            uint2 u0 = *(const uint2*)(h16 + (size_t)s0 * HROW + lane * 4);
            float2 p00 = __half22float2(*(__half2*)&u0.x);
            float2 p01 = __half22float2(*(__half2*)&u0.y);
            acc[0] += w0 * p00.x;
            acc[1] += w0 * p00.y;
            acc[2] += w0 * p01.x;
            acc[3] += w0 * p01.y;
        }
    }
    float inv = 1.f / (ssum + 1e-16f);

    if (!FINAL) {
        float p = prelu_a[0];
        float v[VEC];
#pragma unroll
        for (int j = 0; j < VEC; j++) {
            float t = acc[j] * inv + bias[lane * VEC + j];
            v[j] = (t >= 0.f) ? t : p * t;
        }
        float2 f = make_float2(v[0], v[1]);
        *(float2*)(out + (size_t)warp * 64 + lane * 2) = f;
    } else {
        // mean over heads (lanes stride 4), + bias, log_softmax over 16 ch
        float v[4];
#pragma unroll
        for (int j = 0; j < 4; j++) v[j] = acc[j] * inv;
#pragma unroll
        for (int j = 0; j < 4; j++) {
            v[j] += __shfl_xor_sync(0xffffffffu, v[j], 4);
            v[j] += __shfl_xor_sync(0xffffffffu, v[j], 8);
            v[j] += __shfl_xor_sync(0xffffffffu, v[j], 16);
            v[j] = v[j] * 0.125f + bias[(lane & 3) * 4 + j];
        }
        float mx = fmaxf(fmaxf(v[0], v[1]), fmaxf(v[2], v[3]));
        mx = fmaxf(mx, __shfl_xor_sync(0xffffffffu, mx, 1));
        mx = fmaxf(mx, __shfl_xor_sync(0xffffffffu, mx, 2));
        float se = 0.f;
#pragma unroll
        for (int j = 0; j < 4; j++) se += __expf(v[j] - mx);
        se += __shfl_xor_sync(0xffffffffu, se, 1);
        se += __shfl_xor_sync(0xffffffffu, se, 2);
        float lse = mx + __logf(se);
        if (lane < 4) {
            float4 f = make_float4(v[0] - lse, v[1] - lse, v[2] - lse, v[3] - lse);
            *(float4*)(out + (size_t)warp * 16 + lane * 4) = f;
        }
    }
}

// ---------------------------------------------------------------------------
// Launch
// ---------------------------------------------------------------------------
extern "C" void kernel_launch(void* const* d_in, const int* in_sizes, int n_in,
                              void* d_out, int out_size)
{
    const float* x   = (const float*)d_in[0];
    const int*   ei  = (const int*)d_in[1];
    const float* W1  = (const float*)d_in[2];
    const float* as1 = (const float*)d_in[3];
    const float* ad1 = (const float*)d_in[4];
    const float* b1  = (const float*)d_in[5];
    const float* W2  = (const float*)d_in[6];
    const float* as2 = (const float*)d_in[7];
    const float* ad2 = (const float*)d_in[8];
    const float* b2  = (const float*)d_in[9];
    const float* W3  = (const float*)d_in[10];
    const float* as3 = (const float*)d_in[11];
    const float* ad3 = (const float*)d_in[12];
    const float* b3  = (const float*)d_in[13];
    const float* p1  = (const float*)d_in[14];
    const float* p2  = (const float*)d_in[15];
    float* out = (float*)d_out;

    void *po, *ph16;
    void *pwh1, *pwl1, *pwh2, *pwl2, *pwh3, *pwl3;
    cudaGetSymbolAddress(&po, g_out);
    cudaGetSymbolAddress(&ph16, g_h16);
    cudaGetSymbolAddress(&pwh1, g_wh1);
    cudaGetSymbolAddress(&pwl1, g_wl1);
    cudaGetSymbolAddress(&pwh2, g_wh2);
    cudaGetSymbolAddress(&pwl2, g_wl2);
    cudaGetSymbolAddress(&pwh3, g_wh3);
    cudaGetSymbolAddress(&pwl3, g_wl3);
    float* o = (float*)po;
    const __half* h16 = (const __half*)ph16;

    const int* esrc = ei;
    const int* edst = ei + NE;

    // dynamic smem opt-in (attribute set, not an allocation)
    cudaFuncSetAttribute(k_gemm_mma<8, 64>,
                         cudaFuncAttributeMaxDynamicSharedMemorySize, GEMM_SMEM);
    cudaFuncSetAttribute(k_gemm_mma<16, 128>,
                         cudaFuncAttributeMaxDynamicSharedMemorySize, GEMM_SMEM);

    int agg_blocks = (NN * 32 + 255) / 256;
    dim3 gg1((NN + 255) / 256, 1);   // 391 CTAs of 256 threads
    dim3 gg3((NN + 255) / 256, 2);

    // Launch order puts gemm1 at position 4 (ncu -s 5 -c 1 capture window).
    k_deg_init<<<(NN + 255) / 256, 256>>>();                              // 1
    k_hist<<<(NE + 255) / 256, 256>>>(edst);                              // 2
    k_wt<<<(64 * 256 + 64 * 320 + 128 * 64 + 255) / 256, 256>>>(W1, W2, W3); // 3

    // Layer-1 GEMM (independent of CSR)
    k_gemm_mma<8, 64><<<gg1, 256, GEMM_SMEM>>>(x, 256, (const float*)0, 0, // 4
                                    (const __nv_bfloat16*)pwh1,
                                    (const __nv_bfloat16*)pwl1, as1, ad1);

    // CSR scan + scatter (coalesced two-level scan)
    k_scan_a<<<SCAN_TILES, SCAN_T>>>();                                   // 5
    k_scan_b<<<1, 256>>>();                                               // 6
    k_scan_c<<<SCAN_TILES, SCAN_T>>>();                                   // 7
    k_scatter<<<(NN + NE + 255) / 256, 256>>>(esrc, edst);                // 8

    // Layer 1 aggregate ; +b1 ; PReLU(p1)
    k_agg<8, false><<<agg_blocks, 256>>>(h16, b1, p1, o);                 // 9

    // Layer 2
    k_gemm_mma<8, 64><<<gg1, 256, GEMM_SMEM>>>(x, 256, o, 64,
                                    (const __nv_bfloat16*)pwh2,
                                    (const __nv_bfloat16*)pwl2, as2, ad2);
    k_agg<8, false><<<agg_blocks, 256>>>(h16, b2, p2, o);

    // Layer 3
    k_gemm_mma<16, 128><<<gg3, 256, GEMM_SMEM>>>(o, 64, (const float*)0, 0,
                                      (const __nv_bfloat16*)pwh3,
                                      (const __nv_bfloat16*)pwl3, as3, ad3);
    k_agg<16, true><<<agg_blocks, 256>>>(h16, b3, (const float*)0, out);
}

// round 13
// speedup vs baseline: 1.5476x; 1.2143x over previous
#include <cuda_runtime.h>
#include <cuda_fp16.h>
#include <cuda_bf16.h>
#include <stdint.h>

// Problem constants
#define NN 100000
#define NE 1600000
#define NE2 (NE + NN)
#define SCAN_T 512
#define SCAN_TILES ((NN + SCAN_T - 1) / SCAN_T)  // 196

// ---------------------------------------------------------------------------
// Scratch (device globals — no allocation allowed)
// ---------------------------------------------------------------------------
__device__ __half g_h16[(size_t)NN * 128]; // fp16 linear output (all layers)
__device__ float  g_out[(size_t)NN * 64];  // per-layer aggregated output
__device__ float  g_asrc[NN * 8];
__device__ float  g_adst[NN * 8];
__device__ int    g_rowptr[NN + 1];
__device__ int    g_cursor[NN];
__device__ int    g_csrc[NE2];
__device__ int    g_cnt[NN];
__device__ int    g_tilesum[SCAN_TILES];
__device__ int    g_tileoff[SCAN_TILES];
// Fragment-ordered B (bf16 hi/lo split), word layout:
//   idx = (((c*NB + nb)*2 + hl)*32 + lane)*2 + w
__device__ uint32_t g_bf1[16 * 8 * 2 * 64];   // K=256: 16 chunks, NB=8
__device__ uint32_t g_bf2[20 * 8 * 2 * 64];   // K=320: 20 chunks, NB=8
__device__ uint32_t g_bf3[4 * 16 * 2 * 64];   // K=64:   4 chunks, NB=16

// ---------------------------------------------------------------------------
// CSR build (dst-sorted adjacency incl. self-loops), reused for all 3 layers
// ---------------------------------------------------------------------------
__global__ void k_deg_init() {
    int i = blockIdx.x * blockDim.x + threadIdx.x;
    if (i < NN) g_cnt[i] = 1;  // self loop
}

__global__ void k_hist(const int* __restrict__ edst) {
    int e = blockIdx.x * blockDim.x + threadIdx.x;
    if (e < NE) atomicAdd(&g_cnt[edst[e]], 1);
}

// Coalesced two-level scan: tile reduce -> scan tile sums -> tile-local scan
__global__ __launch_bounds__(SCAN_T) void k_scan_a() {
    __shared__ int sm[SCAN_T];
    int i = blockIdx.x * SCAN_T + threadIdx.x;
    sm[threadIdx.x] = (i < NN) ? g_cnt[i] : 0;
    __syncthreads();
#pragma unroll
    for (int off = SCAN_T / 2; off > 0; off >>= 1) {
        if (threadIdx.x < off) sm[threadIdx.x] += sm[threadIdx.x + off];
        __syncthreads();
    }
    if (threadIdx.x == 0) g_tilesum[blockIdx.x] = sm[0];
}

__global__ __launch_bounds__(256) void k_scan_b() {
    __shared__ int sm[256];
    int t = threadIdx.x;
    int v = (t < SCAN_TILES) ? g_tilesum[t] : 0;
    sm[t] = v;
    __syncthreads();
#pragma unroll
    for (int off = 1; off < 256; off <<= 1) {
        int u = (t >= off) ? sm[t - off] : 0;
        __syncthreads();
        sm[t] += u;
        __syncthreads();
    }
    if (t < SCAN_TILES) g_tileoff[t] = sm[t] - v;  // exclusive prefix of tiles
    if (t == 255) g_rowptr[NN] = sm[255];
}

__global__ __launch_bounds__(SCAN_T) void k_scan_c() {
    __shared__ int sm[SCAN_T];
    int i = blockIdx.x * SCAN_T + threadIdx.x;
    int v = (i < NN) ? g_cnt[i] : 0;
    sm[threadIdx.x] = v;
    __syncthreads();
#pragma unroll
    for (int off = 1; off < SCAN_T; off <<= 1) {
        int u = (threadIdx.x >= off) ? sm[threadIdx.x - off] : 0;
        __syncthreads();
        sm[threadIdx.x] += u;
        __syncthreads();
    }
    if (i < NN) {
        int ex = g_tileoff[blockIdx.x] + sm[threadIdx.x] - v;  // exclusive
        g_rowptr[i] = ex;
        g_cursor[i] = ex;
    }
}

__global__ void k_scatter(const int* __restrict__ esrc, const int* __restrict__ edst) {
    int i = blockIdx.x * blockDim.x + threadIdx.x;
    if (i < NN) {
        int p = atomicAdd(&g_cursor[i], 1);
        g_csrc[p] = i;  // self loop
    } else if (i < NN + NE) {
        int e = i - NN;
        int d = edst[e];
        int p = atomicAdd(&g_cursor[d], 1);
        g_csrc[p] = esrc[e];
    }
}

// ---------------------------------------------------------------------------
// Fragment-ordered B precompute: transpose + bf16 hi/lo split + mma layout.
// For (c, nb, hl, lane, w): n = nb*8 + (lane>>2), k = c*16 + w*8 + (lane&3)*2
// packed bf16x2 of W[k][n], W[k+1][n] (hi: truncated; lo: rn of residual).
// ---------------------------------------------------------------------------
__device__ __forceinline__ uint32_t packpair(float w0, float w1, int hl) {
    uint32_t u0 = __float_as_uint(w0), u1 = __float_as_uint(w1);
    if (hl == 0) return (u0 >> 16) | (u1 & 0xffff0000u);
    float l0 = w0 - __uint_as_float(u0 & 0xffff0000u);
    float l1 = w1 - __uint_as_float(u1 & 0xffff0000u);
    __nv_bfloat162 lb = __floats2bfloat162_rn(l0, l1);
    return *reinterpret_cast<uint32_t*>(&lb);
}

__global__ void k_wfrag(const float* __restrict__ W1,
                        const float* __restrict__ W2,
                        const float* __restrict__ W3) {
    int i = blockIdx.x * blockDim.x + threadIdx.x;
    const float* W; uint32_t* out; int M, NB, rel;
    if (i < 16384)              { W = W1; out = g_bf1; M = 64;  NB = 8;  rel = i; }
    else if (i < 16384 + 20480) { W = W2; out = g_bf2; M = 64;  NB = 8;  rel = i - 16384; }
    else if (i < 45056)         { W = W3; out = g_bf3; M = 128; NB = 16; rel = i - 36864; }
    else return;
    int w    = rel & 1;
    int lane = (rel >> 1) & 31;
    int hl   = (rel >> 6) & 1;
    int nb   = (rel >> 7) % NB;
    int c    = rel / (NB * 128);
    int g = lane >> 2, tg = lane & 3;
    int n = nb * 8 + g;
    int k = c * 16 + w * 8 + tg * 2;
    out[rel] = packpair(W[k * M + n], W[(k + 1) * M + n], hl);
}

// ---------------------------------------------------------------------------
// mma.sync bf16 GEMM, 3-term split, M=32/warp (2 m-tiles), 256-thr CTA.
// A: direct per-lane LDGs (round-9 form, ptxas hoists). B: fragment-ordered
// coalesced LDG.64s from g_bf* (L1/L2-resident).
// Output: h16 (fp16) + fused attention dots a_src/a_dst (fp32 from accs).
// ---------------------------------------------------------------------------
#define MMA_BF16(c, a, b)                                                     \
    asm volatile(                                                             \
        "mma.sync.aligned.m16n8k16.row.col.f32.bf16.bf16.f32 "                \
        "{%0,%1,%2,%3}, {%4,%5,%6,%7}, {%8,%9}, {%0,%1,%2,%3};"               \
        : "+f"((c)[0]), "+f"((c)[1]), "+f"((c)[2]), "+f"((c)[3])              \
        : "r"((a)[0]), "r"((a)[1]), "r"((a)[2]), "r"((a)[3]),                 \
          "r"((b)[0]), "r"((b)[1]))

__device__ __forceinline__ void split2(float2 f, uint32_t& hi, uint32_t& lo) {
    uint32_t u0 = __float_as_uint(f.x), u1 = __float_as_uint(f.y);
    hi = (u0 >> 16) | (u1 & 0xffff0000u);  // packed bf16x2 (truncated)
    float l0 = f.x - __uint_as_float(u0 & 0xffff0000u);
    float l1 = f.y - __uint_as_float(u1 & 0xffff0000u);
    __nv_bfloat162 lb = __floats2bfloat162_rn(l0, l1);
    lo = *reinterpret_cast<uint32_t*>(&lb);
}

template <int CH, int HROW, int NBT>
__global__ __launch_bounds__(256) void k_gemm_mma(
    const float* __restrict__ A1, int K1,
    const float* __restrict__ A2, int K2,
    const uint32_t* __restrict__ Bf,
    const float* __restrict__ ats,
    const float* __restrict__ atd)
{
    int tid = threadIdx.x;
    int wid = tid >> 5, lane = tid & 31;
    int g = lane >> 2, tg = lane & 3;
    int warpRow = blockIdx.x * 256 + wid * 32;
    int colBase = blockIdx.y * 64;
    int nbBase = blockIdx.y * 8;
    int Ktot = K1 + K2;
    int nch = Ktot >> 4;

    float acc[2][8][4];
#pragma unroll
    for (int mt = 0; mt < 2; mt++)
#pragma unroll
        for (int nb = 0; nb < 8; nb++)
#pragma unroll
            for (int j = 0; j < 4; j++) acc[mt][nb][j] = 0.f;

    for (int c = 0; c < nch; c++) {
        int kbase = c << 4;
        const float* src; int stride, koff;
        if (kbase < K1) { src = A1; stride = K1; koff = kbase; }
        else            { src = A2; stride = K2; koff = kbase - K1; }

        // B fragments: coalesced LDG.64 per (nb, hi/lo)
        uint32_t bh[8][2], bl[8][2];
        const uint32_t* bp = Bf + ((size_t)(c * NBT + nbBase) * 2) * 64 + lane * 2;
#pragma unroll
        for (int nb = 0; nb < 8; nb++) {
            uint2 h2 = *(const uint2*)(bp + nb * 128);
            uint2 l2 = *(const uint2*)(bp + nb * 128 + 64);
            bh[nb][0] = h2.x; bh[nb][1] = h2.y;
            bl[nb][0] = l2.x; bl[nb][1] = l2.y;
        }

#pragma unroll
        for (int mt = 0; mt < 2; mt++) {
            int r0 = warpRow + mt * 16 + g;
            int r1 = r0 + 8;
            if (r0 >= NN) r0 = NN - 1;
            if (r1 >= NN) r1 = NN - 1;
            const float* p0 = src + (size_t)r0 * stride + koff + tg * 2;
            const float* p1 = src + (size_t)r1 * stride + koff + tg * 2;
            float2 f0 = *(const float2*)p0;
            float2 f1 = *(const float2*)p1;
            float2 f2 = *(const float2*)(p0 + 8);
            float2 f3 = *(const float2*)(p1 + 8);
            uint32_t ah[4], al[4];
            split2(f0, ah[0], al[0]);
            split2(f1, ah[1], al[1]);
            split2(f2, ah[2], al[2]);
            split2(f3, ah[3], al[3]);
#pragma unroll
            for (int nb = 0; nb < 8; nb++) {
                MMA_BF16(acc[mt][nb], ah, bh[nb]);
                MMA_BF16(acc[mt][nb], ah, bl[nb]);
                MMA_BF16(acc[mt][nb], al, bh[nb]);
            }
        }
    }

    // att weights for this lane's columns: ats/atd laid out so index == col
    float ws[8][2], wd[8][2];
#pragma unroll
    for (int nb = 0; nb < 8; nb++) {
        int col = colBase + nb * 8 + tg * 2;
        float2 a = *(const float2*)(ats + col);
        float2 b = *(const float2*)(atd + col);
        ws[nb][0] = a.x; ws[nb][1] = a.y;
        wd[nb][0] = b.x; wd[nb][1] = b.y;
    }

#pragma unroll
    for (int mt = 0; mt < 2; mt++) {
        int r0 = warpRow + mt * 16 + g;
        int r1 = r0 + 8;
        // emit h16
#pragma unroll
        for (int nb = 0; nb < 8; nb++) {
            int col = colBase + nb * 8 + tg * 2;
            if (r0 < NN)
                *(__half2*)(g_h16 + (size_t)r0 * HROW + col) =
                    __floats2half2_rn(acc[mt][nb][0], acc[mt][nb][1]);
            if (r1 < NN)
                *(__half2*)(g_h16 + (size_t)r1 * HROW + col) =
                    __floats2half2_rn(acc[mt][nb][2], acc[mt][nb][3]);
        }
        // fused attention dots: per-head partials, reduced over tg lanes
        float s0[8], d0[8], s1[8], d1[8];
#pragma unroll
        for (int nb = 0; nb < 8; nb++) {
            s0[nb] = acc[mt][nb][0] * ws[nb][0] + acc[mt][nb][1] * ws[nb][1];
            d0[nb] = acc[mt][nb][0] * wd[nb][0] + acc[mt][nb][1] * wd[nb][1];
            s1[nb] = acc[mt][nb][2] * ws[nb][0] + acc[mt][nb][3] * ws[nb][1];
            d1[nb] = acc[mt][nb][2] * wd[nb][0] + acc[mt][nb][3] * wd[nb][1];
        }
        if (CH == 8) {
            // head == nb
#pragma unroll
            for (int nb = 0; nb < 8; nb++) {
#pragma unroll
                for (int dlt = 1; dlt <= 2; dlt <<= 1) {
                    s0[nb] += __shfl_xor_sync(0xffffffffu, s0[nb], dlt);
                    d0[nb] += __shfl_xor_sync(0xffffffffu, d0[nb], dlt);
                    s1[nb] += __shfl_xor_sync(0xffffffffu, s1[nb], dlt);
                    d1[nb] += __shfl_xor_sync(0xffffffffu, d1[nb], dlt);
                }
            }
            if (r0 < NN) {
                g_asrc[r0 * 8 + tg]     = s0[tg];
                g_asrc[r0 * 8 + tg + 4] = s0[tg + 4];
                g_adst[r0 * 8 + tg]     = d0[tg];
                g_adst[r0 * 8 + tg + 4] = d0[tg + 4];
            }
            if (r1 < NN) {
                g_asrc[r1 * 8 + tg]     = s1[tg];
                g_asrc[r1 * 8 + tg + 4] = s1[tg + 4];
                g_adst[r1 * 8 + tg]     = d1[tg];
                g_adst[r1 * 8 + tg + 4] = d1[tg + 4];
            }
        } else {
            // CH == 16: head spans 2 nb; 4 heads per 64-col block
            int headBase = colBase >> 4;
            float hs0[4], hd0[4], hs1[4], hd1[4];
#pragma unroll
            for (int hh = 0; hh < 4; hh++) {
                hs0[hh] = s0[2 * hh] + s0[2 * hh + 1];
                hd0[hh] = d0[2 * hh] + d0[2 * hh + 1];
                hs1[hh] = s1[2 * hh] + s1[2 * hh + 1];
                hd1[hh] = d1[2 * hh] + d1[2 * hh + 1];
#pragma unroll
                for (int dlt = 1; dlt <= 2; dlt <<= 1) {
                    hs0[hh] += __shfl_xor_sync(0xffffffffu, hs0[hh], dlt);
                    hd0[hh] += __shfl_xor_sync(0xffffffffu, hd0[hh], dlt);
                    hs1[hh] += __shfl_xor_sync(0xffffffffu, hs1[hh], dlt);
                    hd1[hh] += __shfl_xor_sync(0xffffffffu, hd1[hh], dlt);
                }
            }
            if (r0 < NN) {
                g_asrc[r0 * 8 + headBase + tg] = hs0[tg];
                g_adst[r0 * 8 + headBase + tg] = hd0[tg];
            }
            if (r1 < NN) {
                g_asrc[r1 * 8 + headBase + tg] = hs1[tg];
                g_adst[r1 * 8 + headBase + tg] = hd1[tg];
            }
        }
    }
}

// ---------------------------------------------------------------------------
// Aggregation, ONE-PASS softmax (logits clamped at 70), fp16 h gather.
// One warp per dst node; 2-edge pipeline.
// FINAL: head-mean + bias + log_softmax fused.
// ---------------------------------------------------------------------------
template <int C, bool FINAL>
__global__ __launch_bounds__(256) void k_agg(
    const __half* __restrict__ h16,
    const float* __restrict__ bias,
    const float* __restrict__ prelu_a,
    float* __restrict__ out)
{
    constexpr int VEC = C / 4;
    constexpr int HROW = C * 8;
    int warp = (blockIdx.x * blockDim.x + threadIdx.x) >> 5;
    if (warp >= NN) return;
    int lane = threadIdx.x & 31;
    int head = lane >> 2;

    int beg = g_rowptr[warp];
    int end = g_rowptr[warp + 1];
    float ad = g_adst[warp * 8 + head];

    float ssum = 0.f;
    float acc[VEC];
#pragma unroll
    for (int j = 0; j < VEC; j++) acc[j] = 0.f;

    int i = beg;
    for (; i + 2 <= end; i += 2) {
        int s0 = g_csrc[i];
        int s1 = g_csrc[i + 1];
        float a0 = g_asrc[s0 * 8 + head];
        float a1 = g_asrc[s1 * 8 + head];
        float e0 = a0 + ad; e0 = (e0 < 0.f) ? 0.2f * e0 : e0;
        float e1 = a1 + ad; e1 = (e1 < 0.f) ? 0.2f * e1 : e1;
        float w0 = __expf(fminf(e0, 70.f));
        float w1 = __expf(fminf(e1, 70.f));
        ssum += w0 + w1;
        if (!FINAL) {
            uint32_t u0 = *(const uint32_t*)(h16 + (size_t)s0 * HROW + lane * 2);
            uint32_t u1 = *(const uint32_t*)(h16 + (size_t)s1 * HROW + lane * 2);
            float2 p0 = __half22float2(*(__half2*)&u0);
            float2 p1 = __half22float2(*(__half2*)&u1);
            acc[0] += w0 * p0.x + w1 * p1.x;
            acc[1] += w0 * p0.y + w1 * p1.y;
        } else {
            uint2 u0 = *(const uint2*)(h16 + (size_t)s0 * HROW + lane * 4);
            uint2 u1 = *(const uint2*)(h16 + (size_t)s1 * HROW + lane * 4);
            float2 p00 = __half22float2(*(__half2*)&u0.x);
            float2 p01 = __half22float2(*(__half2*)&u0.y);
            float2 p10 = __half22float2(*(__half2*)&u1.x);
            float2 p11 = __half22float2(*(__half2*)&u1.y);
            acc[0] += w0 * p00.x + w1 * p10.x;
            acc[1] += w0 * p00.y + w1 * p10.y;
            acc[2] += w0 * p01.x + w1 * p11.x;
            acc[3] += w0 * p01.y + w1 * p11.y;
        }
    }
    if (i < end) {
        int s0 = g_csrc[i];
        float a0 = g_asrc[s0 * 8 + head];
        float e0 = a0 + ad; e0 = (e0 < 0.f) ? 0.2f * e0 : e0;
        float w0 = __expf(fminf(e0, 70.f));
        ssum += w0;
        if (!FINAL) {
            uint32_t u0 = *(const uint32_t*)(h16 + (size_t)s0 * HROW + lane * 2);
            float2 p0 = __half22float2(*(__half2*)&u0);
            acc[0] += w0 * p0.x;
            acc[1] += w0 * p0.y;
        } else {
            uint2 u0 = *(const uint2*)(h16 + (size_t)s0 * HROW + lane * 4);
            float2 p00 = __half22float2(*(__half2*)&u0.x);
            float2 p01 = __half22float2(*(__half2*)&u0.y);
            acc[0] += w0 * p00.x;
            acc[1] += w0 * p00.y;
            acc[2] += w0 * p01.x;
            acc[3] += w0 * p01.y;
        }
    }
    float inv = 1.f / (ssum + 1e-16f);

    if (!FINAL) {
        float p = prelu_a[0];
        float v[VEC];
#pragma unroll
        for (int j = 0; j < VEC; j++) {
            float t = acc[j] * inv + bias[lane * VEC + j];
            v[j] = (t >= 0.f) ? t : p * t;
        }
        float2 f = make_float2(v[0], v[1]);
        *(float2*)(out + (size_t)warp * 64 + lane * 2) = f;
    } else {
        // mean over heads (lanes stride 4), + bias, log_softmax over 16 ch
        float v[4];
#pragma unroll
        for (int j = 0; j < 4; j++) v[j] = acc[j] * inv;
#pragma unroll
        for (int j = 0; j < 4; j++) {
            v[j] += __shfl_xor_sync(0xffffffffu, v[j], 4);
            v[j] += __shfl_xor_sync(0xffffffffu, v[j], 8);
            v[j] += __shfl_xor_sync(0xffffffffu, v[j], 16);
            v[j] = v[j] * 0.125f + bias[(lane & 3) * 4 + j];
        }
        float mx = fmaxf(fmaxf(v[0], v[1]), fmaxf(v[2], v[3]));
        mx = fmaxf(mx, __shfl_xor_sync(0xffffffffu, mx, 1));
        mx = fmaxf(mx, __shfl_xor_sync(0xffffffffu, mx, 2));
        float se = 0.f;
#pragma unroll
        for (int j = 0; j < 4; j++) se += __expf(v[j] - mx);
        se += __shfl_xor_sync(0xffffffffu, se, 1);
        se += __shfl_xor_sync(0xffffffffu, se, 2);
        float lse = mx + __logf(se);
        if (lane < 4) {
            float4 f = make_float4(v[0] - lse, v[1] - lse, v[2] - lse, v[3] - lse);
            *(float4*)(out + (size_t)warp * 16 + lane * 4) = f;
        }
    }
}

// ---------------------------------------------------------------------------
// Launch
// ---------------------------------------------------------------------------
extern "C" void kernel_launch(void* const* d_in, const int* in_sizes, int n_in,
                              void* d_out, int out_size)
{
    const float* x   = (const float*)d_in[0];
    const int*   ei  = (const int*)d_in[1];
    const float* W1  = (const float*)d_in[2];
    const float* as1 = (const float*)d_in[3];
    const float* ad1 = (const float*)d_in[4];
    const float* b1  = (const float*)d_in[5];
    const float* W2  = (const float*)d_in[6];
    const float* as2 = (const float*)d_in[7];
    const float* ad2 = (const float*)d_in[8];
    const float* b2  = (const float*)d_in[9];
    const float* W3  = (const float*)d_in[10];
    const float* as3 = (const float*)d_in[11];
    const float* ad3 = (const float*)d_in[12];
    const float* b3  = (const float*)d_in[13];
    const float* p1  = (const float*)d_in[14];
    const float* p2  = (const float*)d_in[15];
    float* out = (float*)d_out;

    void *po, *ph16, *pb1, *pb2, *pb3;
    cudaGetSymbolAddress(&po, g_out);
    cudaGetSymbolAddress(&ph16, g_h16);
    cudaGetSymbolAddress(&pb1, g_bf1);
    cudaGetSymbolAddress(&pb2, g_bf2);
    cudaGetSymbolAddress(&pb3, g_bf3);
    float* o = (float*)po;
    const __half* h16 = (const __half*)ph16;

    const int* esrc = ei;
    const int* edst = ei + NE;

    int agg_blocks = (NN * 32 + 255) / 256;
    dim3 gg1((NN + 255) / 256, 1);   // 391 CTAs of 256 threads
    dim3 gg3((NN + 255) / 256, 2);

    // Launch order puts gemm1 at position 4 (ncu -s 5 -c 1 capture window).
    k_deg_init<<<(NN + 255) / 256, 256>>>();                              // 1
    k_hist<<<(NE + 255) / 256, 256>>>(edst);                              // 2
    k_wfrag<<<(45056 + 255) / 256, 256>>>(W1, W2, W3);                    // 3

    // Layer-1 GEMM (independent of CSR)
    k_gemm_mma<8, 64, 8><<<gg1, 256>>>(x, 256, (const float*)0, 0,        // 4
                                       (const uint32_t*)pb1, as1, ad1);

    // CSR scan + scatter (coalesced two-level scan)
    k_scan_a<<<SCAN_TILES, SCAN_T>>>();                                   // 5
    k_scan_b<<<1, 256>>>();                                               // 6
    k_scan_c<<<SCAN_TILES, SCAN_T>>>();                                   // 7
    k_scatter<<<(NN + NE + 255) / 256, 256>>>(esrc, edst);                // 8

    // Layer 1 aggregate ; +b1 ; PReLU(p1)
    k_agg<8, false><<<agg_blocks, 256>>>(h16, b1, p1, o);                 // 9

    // Layer 2
    k_gemm_mma<8, 64, 8><<<gg1, 256>>>(x, 256, o, 64,
                                       (const uint32_t*)pb2, as2, ad2);
    k_agg<8, false><<<agg_blocks, 256>>>(h16, b2, p2, o);

    // Layer 3
    k_gemm_mma<16, 128, 16><<<gg3, 256>>>(o, 64, (const float*)0, 0,
                                          (const uint32_t*)pb3, as3, ad3);
    k_agg<16, true><<<agg_blocks, 256>>>(h16, b3, (const float*)0, out);
}

// round 14
// speedup vs baseline: 1.7178x; 1.1100x over previous
#include <cuda_runtime.h>
#include <cuda_fp16.h>
#include <cuda_bf16.h>
#include <stdint.h>

// Problem constants
#define NN 100000
#define NE 1600000
#define NE2 (NE + NN)
#define SCAN_T 512
#define SCAN_TILES ((NN + SCAN_T - 1) / SCAN_T)  // 196

// ---------------------------------------------------------------------------
// Scratch (device globals — no allocation allowed)
// ---------------------------------------------------------------------------
__device__ __half g_h16[(size_t)NN * 128]; // fp16 linear output (all layers)
__device__ float  g_out[(size_t)NN * 64];  // per-layer aggregated output
__device__ float  g_asrc[NN * 8];
__device__ float  g_adst[NN * 8];
__device__ int    g_rowptr[NN + 1];
__device__ int    g_cursor[NN];
__device__ int    g_csrc[NE2];
__device__ int    g_cnt[NN];
__device__ int    g_tilesum[SCAN_TILES];
__device__ int    g_tileoff[SCAN_TILES];
// Fragment-ordered B (bf16 hi/lo split), word layout:
//   idx = (((c*NB + nb)*2 + hl)*32 + lane)*2 + w
__device__ uint32_t g_bf1[16 * 8 * 2 * 64];   // K=256: 16 chunks, NB=8
__device__ uint32_t g_bf2[20 * 8 * 2 * 64];   // K=320: 20 chunks, NB=8
__device__ uint32_t g_bf3[4 * 16 * 2 * 64];   // K=64:   4 chunks, NB=16

// ---------------------------------------------------------------------------
// CSR build (dst-sorted adjacency incl. self-loops), reused for all 3 layers
// ---------------------------------------------------------------------------
__global__ void k_deg_init() {
    int i = blockIdx.x * blockDim.x + threadIdx.x;
    if (i < NN) g_cnt[i] = 1;  // self loop
}

__global__ void k_hist(const int* __restrict__ edst) {
    int e = blockIdx.x * blockDim.x + threadIdx.x;
    if (e < NE) atomicAdd(&g_cnt[edst[e]], 1);
}

// Coalesced two-level scan: tile reduce -> scan tile sums -> tile-local scan
__global__ __launch_bounds__(SCAN_T) void k_scan_a() {
    __shared__ int sm[SCAN_T];
    int i = blockIdx.x * SCAN_T + threadIdx.x;
    sm[threadIdx.x] = (i < NN) ? g_cnt[i] : 0;
    __syncthreads();
#pragma unroll
    for (int off = SCAN_T / 2; off > 0; off >>= 1) {
        if (threadIdx.x < off) sm[threadIdx.x] += sm[threadIdx.x + off];
        __syncthreads();
    }
    if (threadIdx.x == 0) g_tilesum[blockIdx.x] = sm[0];
}

__global__ __launch_bounds__(256) void k_scan_b() {
    __shared__ int sm[256];
    int t = threadIdx.x;
    int v = (t < SCAN_TILES) ? g_tilesum[t] : 0;
    sm[t] = v;
    __syncthreads();
#pragma unroll
    for (int off = 1; off < 256; off <<= 1) {
        int u = (t >= off) ? sm[t - off] : 0;
        __syncthreads();
        sm[t] += u;
        __syncthreads();
    }
    if (t < SCAN_TILES) g_tileoff[t] = sm[t] - v;  // exclusive prefix of tiles
    if (t == 255) g_rowptr[NN] = sm[255];
}

__global__ __launch_bounds__(SCAN_T) void k_scan_c() {
    __shared__ int sm[SCAN_T];
    int i = blockIdx.x * SCAN_T + threadIdx.x;
    int v = (i < NN) ? g_cnt[i] : 0;
    sm[threadIdx.x] = v;
    __syncthreads();
#pragma unroll
    for (int off = 1; off < SCAN_T; off <<= 1) {
        int u = (threadIdx.x >= off) ? sm[threadIdx.x - off] : 0;
        __syncthreads();
        sm[threadIdx.x] += u;
        __syncthreads();
    }
    if (i < NN) {
        int ex = g_tileoff[blockIdx.x] + sm[threadIdx.x] - v;  // exclusive
        g_rowptr[i] = ex;
        g_cursor[i] = ex;
    }
}

__global__ void k_scatter(const int* __restrict__ esrc, const int* __restrict__ edst) {
    int i = blockIdx.x * blockDim.x + threadIdx.x;
    if (i < NN) {
        int p = atomicAdd(&g_cursor[i], 1);
        g_csrc[p] = i;  // self loop
    } else if (i < NN + NE) {
        int e = i - NN;
        int d = edst[e];
        int p = atomicAdd(&g_cursor[d], 1);
        g_csrc[p] = esrc[e];
    }
}

// ---------------------------------------------------------------------------
// Fragment-ordered B precompute: transpose + bf16 hi/lo split + mma layout.
// For (c, nb, hl, lane, w): n = nb*8 + (lane>>2), k = c*16 + w*8 + (lane&3)*2
// packed bf16x2 of W[k][n], W[k+1][n] (hi: truncated; lo: rn of residual).
// ---------------------------------------------------------------------------
__device__ __forceinline__ uint32_t packpair(float w0, float w1, int hl) {
    uint32_t u0 = __float_as_uint(w0), u1 = __float_as_uint(w1);
    if (hl == 0) return (u0 >> 16) | (u1 & 0xffff0000u);
    float l0 = w0 - __uint_as_float(u0 & 0xffff0000u);
    float l1 = w1 - __uint_as_float(u1 & 0xffff0000u);
    __nv_bfloat162 lb = __floats2bfloat162_rn(l0, l1);
    return *reinterpret_cast<uint32_t*>(&lb);
}

__global__ void k_wfrag(const float* __restrict__ W1,
                        const float* __restrict__ W2,
                        const float* __restrict__ W3) {
    int i = blockIdx.x * blockDim.x + threadIdx.x;
    const float* W; uint32_t* out; int M, NB, rel;
    if (i < 16384)              { W = W1; out = g_bf1; M = 64;  NB = 8;  rel = i; }
    else if (i < 16384 + 20480) { W = W2; out = g_bf2; M = 64;  NB = 8;  rel = i - 16384; }
    else if (i < 45056)         { W = W3; out = g_bf3; M = 128; NB = 16; rel = i - 36864; }
    else return;
    int w    = rel & 1;
    int lane = (rel >> 1) & 31;
    int hl   = (rel >> 6) & 1;
    int nb   = (rel >> 7) % NB;
    int c    = rel / (NB * 128);
    int g = lane >> 2, tg = lane & 3;
    int n = nb * 8 + g;
    int k = c * 16 + w * 8 + tg * 2;
    out[rel] = packpair(W[k * M + n], W[(k + 1) * M + n], hl);
}

// ---------------------------------------------------------------------------
// mma.sync bf16 GEMM, 3-term split, M=32/warp (2 m-tiles), 256-thr CTA,
// __launch_bounds__(256,2) to force 2 CTAs/SM (16 warps -> 2x A-stream MLP).
// A: direct per-lane LDGs. B: fragment-ordered coalesced LDG.64s (L1/L2-res).
// Output: h16 (fp16) + fused attention dots a_src/a_dst (fp32 from accs).
// ---------------------------------------------------------------------------
#define MMA_BF16(c, a, b)                                                     \
    asm volatile(                                                             \
        "mma.sync.aligned.m16n8k16.row.col.f32.bf16.bf16.f32 "                \
        "{%0,%1,%2,%3}, {%4,%5,%6,%7}, {%8,%9}, {%0,%1,%2,%3};"               \
        : "+f"((c)[0]), "+f"((c)[1]), "+f"((c)[2]), "+f"((c)[3])              \
        : "r"((a)[0]), "r"((a)[1]), "r"((a)[2]), "r"((a)[3]),                 \
          "r"((b)[0]), "r"((b)[1]))

__device__ __forceinline__ void split2(float2 f, uint32_t& hi, uint32_t& lo) {
    uint32_t u0 = __float_as_uint(f.x), u1 = __float_as_uint(f.y);
    hi = (u0 >> 16) | (u1 & 0xffff0000u);  // packed bf16x2 (truncated)
    float l0 = f.x - __uint_as_float(u0 & 0xffff0000u);
    float l1 = f.y - __uint_as_float(u1 & 0xffff0000u);
    __nv_bfloat162 lb = __floats2bfloat162_rn(l0, l1);
    lo = *reinterpret_cast<uint32_t*>(&lb);
}

template <int CH, int HROW, int NBT>
__global__ __launch_bounds__(256, 2) void k_gemm_mma(
    const float* __restrict__ A1, int K1,
    const float* __restrict__ A2, int K2,
    const uint32_t* __restrict__ Bf,
    const float* __restrict__ ats,
    const float* __restrict__ atd)
{
    int tid = threadIdx.x;
    int wid = tid >> 5, lane = tid & 31;
    int g = lane >> 2, tg = lane & 3;
    int warpRow = blockIdx.x * 256 + wid * 32;
    int colBase = blockIdx.y * 64;
    int nbBase = blockIdx.y * 8;
    int Ktot = K1 + K2;
    int nch = Ktot >> 4;

    float acc[2][8][4];
#pragma unroll
    for (int mt = 0; mt < 2; mt++)
#pragma unroll
        for (int nb = 0; nb < 8; nb++)
#pragma unroll
            for (int j = 0; j < 4; j++) acc[mt][nb][j] = 0.f;

    for (int c = 0; c < nch; c++) {
        int kbase = c << 4;
        const float* src; int stride, koff;
        if (kbase < K1) { src = A1; stride = K1; koff = kbase; }
        else            { src = A2; stride = K2; koff = kbase - K1; }

        // B fragments: coalesced LDG.64 per (nb, hi/lo)
        uint32_t bh[8][2], bl[8][2];
        const uint32_t* bp = Bf + ((size_t)(c * NBT + nbBase) * 2) * 64 + lane * 2;
#pragma unroll
        for (int nb = 0; nb < 8; nb++) {
            uint2 h2 = *(const uint2*)(bp + nb * 128);
            uint2 l2 = *(const uint2*)(bp + nb * 128 + 64);
            bh[nb][0] = h2.x; bh[nb][1] = h2.y;
            bl[nb][0] = l2.x; bl[nb][1] = l2.y;
        }

#pragma unroll
        for (int mt = 0; mt < 2; mt++) {
            int r0 = warpRow + mt * 16 + g;
            int r1 = r0 + 8;
            if (r0 >= NN) r0 = NN - 1;
            if (r1 >= NN) r1 = NN - 1;
            const float* p0 = src + (size_t)r0 * stride + koff + tg * 2;
            const float* p1 = src + (size_t)r1 * stride + koff + tg * 2;
            float2 f0 = *(const float2*)p0;
            float2 f1 = *(const float2*)p1;
            float2 f2 = *(const float2*)(p0 + 8);
            float2 f3 = *(const float2*)(p1 + 8);
            uint32_t ah[4], al[4];
            split2(f0, ah[0], al[0]);
            split2(f1, ah[1], al[1]);
            split2(f2, ah[2], al[2]);
            split2(f3, ah[3], al[3]);
#pragma unroll
            for (int nb = 0; nb < 8; nb++) {
                MMA_BF16(acc[mt][nb], ah, bh[nb]);
                MMA_BF16(acc[mt][nb], ah, bl[nb]);
                MMA_BF16(acc[mt][nb], al, bh[nb]);
            }
        }
    }

    // att weights for this lane's columns: ats/atd laid out so index == col
    float ws[8][2], wd[8][2];
#pragma unroll
    for (int nb = 0; nb < 8; nb++) {
        int col = colBase + nb * 8 + tg * 2;
        float2 a = *(const float2*)(ats + col);
        float2 b = *(const float2*)(atd + col);
        ws[nb][0] = a.x; ws[nb][1] = a.y;
        wd[nb][0] = b.x; wd[nb][1] = b.y;
    }

#pragma unroll
    for (int mt = 0; mt < 2; mt++) {
        int r0 = warpRow + mt * 16 + g;
        int r1 = r0 + 8;
        // emit h16
#pragma unroll
        for (int nb = 0; nb < 8; nb++) {
            int col = colBase + nb * 8 + tg * 2;
            if (r0 < NN)
                *(__half2*)(g_h16 + (size_t)r0 * HROW + col) =
                    __floats2half2_rn(acc[mt][nb][0], acc[mt][nb][1]);
            if (r1 < NN)
                *(__half2*)(g_h16 + (size_t)r1 * HROW + col) =
                    __floats2half2_rn(acc[mt][nb][2], acc[mt][nb][3]);
        }
        // fused attention dots: per-head partials, reduced over tg lanes
        float s0[8], d0[8], s1[8], d1[8];
#pragma unroll
        for (int nb = 0; nb < 8; nb++) {
            s0[nb] = acc[mt][nb][0] * ws[nb][0] + acc[mt][nb][1] * ws[nb][1];
            d0[nb] = acc[mt][nb][0] * wd[nb][0] + acc[mt][nb][1] * wd[nb][1];
            s1[nb] = acc[mt][nb][2] * ws[nb][0] + acc[mt][nb][3] * ws[nb][1];
            d1[nb] = acc[mt][nb][2] * wd[nb][0] + acc[mt][nb][3] * wd[nb][1];
        }
        if (CH == 8) {
            // head == nb
#pragma unroll
            for (int nb = 0; nb < 8; nb++) {
#pragma unroll
                for (int dlt = 1; dlt <= 2; dlt <<= 1) {
                    s0[nb] += __shfl_xor_sync(0xffffffffu, s0[nb], dlt);
                    d0[nb] += __shfl_xor_sync(0xffffffffu, d0[nb], dlt);
                    s1[nb] += __shfl_xor_sync(0xffffffffu, s1[nb], dlt);
                    d1[nb] += __shfl_xor_sync(0xffffffffu, d1[nb], dlt);
                }
            }
            if (r0 < NN) {
                g_asrc[r0 * 8 + tg]     = s0[tg];
                g_asrc[r0 * 8 + tg + 4] = s0[tg + 4];
                g_adst[r0 * 8 + tg]     = d0[tg];
                g_adst[r0 * 8 + tg + 4] = d0[tg + 4];
            }
            if (r1 < NN) {
                g_asrc[r1 * 8 + tg]     = s1[tg];
                g_asrc[r1 * 8 + tg + 4] = s1[tg + 4];
                g_adst[r1 * 8 + tg]     = d1[tg];
                g_adst[r1 * 8 + tg + 4] = d1[tg + 4];
            }
        } else {
            // CH == 16: head spans 2 nb; 4 heads per 64-col block
            int headBase = colBase >> 4;
            float hs0[4], hd0[4], hs1[4], hd1[4];
#pragma unroll
            for (int hh = 0; hh < 4; hh++) {
                hs0[hh] = s0[2 * hh] + s0[2 * hh + 1];
                hd0[hh] = d0[2 * hh] + d0[2 * hh + 1];
                hs1[hh] = s1[2 * hh] + s1[2 * hh + 1];
                hd1[hh] = d1[2 * hh] + d1[2 * hh + 1];
#pragma unroll
                for (int dlt = 1; dlt <= 2; dlt <<= 1) {
                    hs0[hh] += __shfl_xor_sync(0xffffffffu, hs0[hh], dlt);
                    hd0[hh] += __shfl_xor_sync(0xffffffffu, hd0[hh], dlt);
                    hs1[hh] += __shfl_xor_sync(0xffffffffu, hs1[hh], dlt);
                    hd1[hh] += __shfl_xor_sync(0xffffffffu, hd1[hh], dlt);
                }
            }
            if (r0 < NN) {
                g_asrc[r0 * 8 + headBase + tg] = hs0[tg];
                g_adst[r0 * 8 + headBase + tg] = hd0[tg];
            }
            if (r1 < NN) {
                g_asrc[r1 * 8 + headBase + tg] = hs1[tg];
                g_adst[r1 * 8 + headBase + tg] = hd1[tg];
            }
        }
    }
}

// ---------------------------------------------------------------------------
// Aggregation, ONE-PASS softmax (logits clamped at 70), fp16 h gather.
// One warp per dst node; 2-edge pipeline.
// FINAL: head-mean + bias + log_softmax fused.
// ---------------------------------------------------------------------------
template <int C, bool FINAL>
__global__ __launch_bounds__(256) void k_agg(
    const __half* __restrict__ h16,
    const float* __restrict__ bias,
    const float* __restrict__ prelu_a,
    float* __restrict__ out)
{
    constexpr int VEC = C / 4;
    constexpr int HROW = C * 8;
    int warp = (blockIdx.x * blockDim.x + threadIdx.x) >> 5;
    if (warp >= NN) return;
    int lane = threadIdx.x & 31;
    int head = lane >> 2;

    int beg = g_rowptr[warp];
    int end = g_rowptr[warp + 1];
    float ad = g_adst[warp * 8 + head];

    float ssum = 0.f;
    float acc[VEC];
#pragma unroll
    for (int j = 0; j < VEC; j++) acc[j] = 0.f;

    int i = beg;
    for (; i + 2 <= end; i += 2) {
        int s0 = g_csrc[i];
        int s1 = g_csrc[i + 1];
        float a0 = g_asrc[s0 * 8 + head];
        float a1 = g_asrc[s1 * 8 + head];
        float e0 = a0 + ad; e0 = (e0 < 0.f) ? 0.2f * e0 : e0;
        float e1 = a1 + ad; e1 = (e1 < 0.f) ? 0.2f * e1 : e1;
        float w0 = __expf(fminf(e0, 70.f));
        float w1 = __expf(fminf(e1, 70.f));
        ssum += w0 + w1;
        if (!FINAL) {
            uint32_t u0 = *(const uint32_t*)(h16 + (size_t)s0 * HROW + lane * 2);
            uint32_t u1 = *(const uint32_t*)(h16 + (size_t)s1 * HROW + lane * 2);
            float2 p0 = __half22float2(*(__half2*)&u0);
            float2 p1 = __half22float2(*(__half2*)&u1);
            acc[0] += w0 * p0.x + w1 * p1.x;
            acc[1] += w0 * p0.y + w1 * p1.y;
        } else {
            uint2 u0 = *(const uint2*)(h16 + (size_t)s0 * HROW + lane * 4);
            uint2 u1 = *(const uint2*)(h16 + (size_t)s1 * HROW + lane * 4);
            float2 p00 = __half22float2(*(__half2*)&u0.x);
            float2 p01 = __half22float2(*(__half2*)&u0.y);
            float2 p10 = __half22float2(*(__half2*)&u1.x);
            float2 p11 = __half22float2(*(__half2*)&u1.y);
            acc[0] += w0 * p00.x + w1 * p10.x;
            acc[1] += w0 * p00.y + w1 * p10.y;
            acc[2] += w0 * p01.x + w1 * p11.x;
            acc[3] += w0 * p01.y + w1 * p11.y;
        }
    }
    if (i < end) {
        int s0 = g_csrc[i];
        float a0 = g_asrc[s0 * 8 + head];
        float e0 = a0 + ad; e0 = (e0 < 0.f) ? 0.2f * e0 : e0;
        float w0 = __expf(fminf(e0, 70.f));
        ssum += w0;
        if (!FINAL) {
            uint32_t u0 = *(const uint32_t*)(h16 + (size_t)s0 * HROW + lane * 2);
            float2 p0 = __half22float2(*(__half2*)&u0);
            acc[0] += w0 * p0.x;
            acc[1] += w0 * p0.y;
        } else {
            uint2 u0 = *(const uint2*)(h16 + (size_t)s0 * HROW + lane * 4);
            float2 p00 = __half22float2(*(__half2*)&u0.x);
            float2 p01 = __half22float2(*(__half2*)&u0.y);
            acc[0] += w0 * p00.x;
            acc[1] += w0 * p00.y;
            acc[2] += w0 * p01.x;
            acc[3] += w0 * p01.y;
        }
    }
    float inv = 1.f / (ssum + 1e-16f);

    if (!FINAL) {
        float p = prelu_a[0];
        float v[VEC];
#pragma unroll
        for (int j = 0; j < VEC; j++) {
            float t = acc[j] * inv + bias[lane * VEC + j];
            v[j] = (t >= 0.f) ? t : p * t;
        }
        float2 f = make_float2(v[0], v[1]);
        *(float2*)(out + (size_t)warp * 64 + lane * 2) = f;
    } else {
        // mean over heads (lanes stride 4), + bias, log_softmax over 16 ch
        float v[4];
#pragma unroll
        for (int j = 0; j < 4; j++) v[j] = acc[j] * inv;
#pragma unroll
        for (int j = 0; j < 4; j++) {
            v[j] += __shfl_xor_sync(0xffffffffu, v[j], 4);
            v[j] += __shfl_xor_sync(0xffffffffu, v[j], 8);
            v[j] += __shfl_xor_sync(0xffffffffu, v[j], 16);
            v[j] = v[j] * 0.125f + bias[(lane & 3) * 4 + j];
        }
        float mx = fmaxf(fmaxf(v[0], v[1]), fmaxf(v[2], v[3]));
        mx = fmaxf(mx, __shfl_xor_sync(0xffffffffu, mx, 1));
        mx = fmaxf(mx, __shfl_xor_sync(0xffffffffu, mx, 2));
        float se = 0.f;
#pragma unroll
        for (int j = 0; j < 4; j++) se += __expf(v[j] - mx);
        se += __shfl_xor_sync(0xffffffffu, se, 1);
        se += __shfl_xor_sync(0xffffffffu, se, 2);
        float lse = mx + __logf(se);
        if (lane < 4) {
            float4 f = make_float4(v[0] - lse, v[1] - lse, v[2] - lse, v[3] - lse);
            *(float4*)(out + (size_t)warp * 16 + lane * 4) = f;
        }
    }
}

// ---------------------------------------------------------------------------
// Launch
// ---------------------------------------------------------------------------
extern "C" void kernel_launch(void* const* d_in, const int* in_sizes, int n_in,
                              void* d_out, int out_size)
{
    const float* x   = (const float*)d_in[0];
    const int*   ei  = (const int*)d_in[1];
    const float* W1  = (const float*)d_in[2];
    const float* as1 = (const float*)d_in[3];
    const float* ad1 = (const float*)d_in[4];
    const float* b1  = (const float*)d_in[5];
    const float* W2  = (const float*)d_in[6];
    const float* as2 = (const float*)d_in[7];
    const float* ad2 = (const float*)d_in[8];
    const float* b2  = (const float*)d_in[9];
    const float* W3  = (const float*)d_in[10];
    const float* as3 = (const float*)d_in[11];
    const float* ad3 = (const float*)d_in[12];
    const float* b3  = (const float*)d_in[13];
    const float* p1  = (const float*)d_in[14];
    const float* p2  = (const float*)d_in[15];
    float* out = (float*)d_out;

    void *po, *ph16, *pb1, *pb2, *pb3;
    cudaGetSymbolAddress(&po, g_out);
    cudaGetSymbolAddress(&ph16, g_h16);
    cudaGetSymbolAddress(&pb1, g_bf1);
    cudaGetSymbolAddress(&pb2, g_bf2);
    cudaGetSymbolAddress(&pb3, g_bf3);
    float* o = (float*)po;
    const __half* h16 = (const __half*)ph16;

    const int* esrc = ei;
    const int* edst = ei + NE;

    int agg_blocks = (NN * 32 + 255) / 256;
    dim3 gg1((NN + 255) / 256, 1);   // 391 CTAs of 256 threads
    dim3 gg3((NN + 255) / 256, 2);

    // Launch order puts gemm1 at position 4 (ncu -s 5 -c 1 capture window).
    k_deg_init<<<(NN + 255) / 256, 256>>>();                              // 1
    k_hist<<<(NE + 255) / 256, 256>>>(edst);                              // 2
    k_wfrag<<<(45056 + 255) / 256, 256>>>(W1, W2, W3);                    // 3

    // Layer-1 GEMM (independent of CSR)
    k_gemm_mma<8, 64, 8><<<gg1, 256>>>(x, 256, (const float*)0, 0,        // 4
                                       (const uint32_t*)pb1, as1, ad1);

    // CSR scan + scatter (coalesced two-level scan)
    k_scan_a<<<SCAN_TILES, SCAN_T>>>();                                   // 5
    k_scan_b<<<1, 256>>>();                                               // 6
    k_scan_c<<<SCAN_TILES, SCAN_T>>>();                                   // 7
    k_scatter<<<(NN + NE + 255) / 256, 256>>>(esrc, edst);                // 8

    // Layer 1 aggregate ; +b1 ; PReLU(p1)
    k_agg<8, false><<<agg_blocks, 256>>>(h16, b1, p1, o);                 // 9

    // Layer 2
    k_gemm_mma<8, 64, 8><<<gg1, 256>>>(x, 256, o, 64,
                                       (const uint32_t*)pb2, as2, ad2);
    k_agg<8, false><<<agg_blocks, 256>>>(h16, b2, p2, o);

    // Layer 3
    k_gemm_mma<16, 128, 16><<<gg3, 256>>>(o, 64, (const float*)0, 0,
                                          (const uint32_t*)pb3, as3, ad3);
    k_agg<16, true><<<agg_blocks, 256>>>(h16, b3, (const float*)0, out);
}

// round 15
// speedup vs baseline: 1.7458x; 1.0163x over previous
#include <cuda_runtime.h>
#include <cuda_fp16.h>
#include <cuda_bf16.h>
#include <stdint.h>

// Problem constants
#define NN 100000
#define NE 1600000
#define NE2 (NE + NN)
#define SCAN_T 512
#define SCAN_TILES ((NN + SCAN_T - 1) / SCAN_T)  // 196

// ---------------------------------------------------------------------------
// Scratch (device globals — no allocation allowed)
// ---------------------------------------------------------------------------
__device__ __half g_h16[(size_t)NN * 128]; // fp16 linear output (all layers)
__device__ float  g_out[(size_t)NN * 64];  // per-layer aggregated output
__device__ float  g_asrc[NN * 8];
__device__ float  g_adst[NN * 8];
__device__ int    g_rowptr[NN + 1];
__device__ int    g_cursor[NN];
__device__ int    g_csrc[NE2];
__device__ int    g_cnt[NN];
__device__ int    g_tilesum[SCAN_TILES];
__device__ int    g_tileoff[SCAN_TILES];
// Fragment-ordered B (bf16 hi/lo split), word layout:
//   idx = (((c*NB + nb)*2 + hl)*32 + lane)*2 + w
// k-PERMUTED to match contiguous float4 A loads: logical k = c*16 + tg*4 + w*2
__device__ uint32_t g_bf1[16 * 8 * 2 * 64];   // K=256: 16 chunks, NB=8
__device__ uint32_t g_bf2[20 * 8 * 2 * 64];   // K=320: 20 chunks, NB=8
__device__ uint32_t g_bf3[4 * 16 * 2 * 64];   // K=64:   4 chunks, NB=16

// ---------------------------------------------------------------------------
// CSR build (dst-sorted adjacency incl. self-loops), reused for all 3 layers
// ---------------------------------------------------------------------------
__global__ void k_deg_init() {
    int i = blockIdx.x * blockDim.x + threadIdx.x;
    if (i < NN) g_cnt[i] = 1;  // self loop
}

__global__ void k_hist(const int* __restrict__ edst) {
    int e = blockIdx.x * blockDim.x + threadIdx.x;
    if (e < NE) atomicAdd(&g_cnt[edst[e]], 1);
}

// Coalesced two-level scan: tile reduce -> scan tile sums -> tile-local scan
__global__ __launch_bounds__(SCAN_T) void k_scan_a() {
    __shared__ int sm[SCAN_T];
    int i = blockIdx.x * SCAN_T + threadIdx.x;
    sm[threadIdx.x] = (i < NN) ? g_cnt[i] : 0;
    __syncthreads();
#pragma unroll
    for (int off = SCAN_T / 2; off > 0; off >>= 1) {
        if (threadIdx.x < off) sm[threadIdx.x] += sm[threadIdx.x + off];
        __syncthreads();
    }
    if (threadIdx.x == 0) g_tilesum[blockIdx.x] = sm[0];
}

__global__ __launch_bounds__(256) void k_scan_b() {
    __shared__ int sm[256];
    int t = threadIdx.x;
    int v = (t < SCAN_TILES) ? g_tilesum[t] : 0;
    sm[t] = v;
    __syncthreads();
#pragma unroll
    for (int off = 1; off < 256; off <<= 1) {
        int u = (t >= off) ? sm[t - off] : 0;
        __syncthreads();
        sm[t] += u;
        __syncthreads();
    }
    if (t < SCAN_TILES) g_tileoff[t] = sm[t] - v;  // exclusive prefix of tiles
    if (t == 255) g_rowptr[NN] = sm[255];
}

__global__ __launch_bounds__(SCAN_T) void k_scan_c() {
    __shared__ int sm[SCAN_T];
    int i = blockIdx.x * SCAN_T + threadIdx.x;
    int v = (i < NN) ? g_cnt[i] : 0;
    sm[threadIdx.x] = v;
    __syncthreads();
#pragma unroll
    for (int off = 1; off < SCAN_T; off <<= 1) {
        int u = (threadIdx.x >= off) ? sm[threadIdx.x - off] : 0;
        __syncthreads();
        sm[threadIdx.x] += u;
        __syncthreads();
    }
    if (i < NN) {
        int ex = g_tileoff[blockIdx.x] + sm[threadIdx.x] - v;  // exclusive
        g_rowptr[i] = ex;
        g_cursor[i] = ex;
    }
}

__global__ void k_scatter(const int* __restrict__ esrc, const int* __restrict__ edst) {
    int i = blockIdx.x * blockDim.x + threadIdx.x;
    if (i < NN) {
        int p = atomicAdd(&g_cursor[i], 1);
        g_csrc[p] = i;  // self loop
    } else if (i < NN + NE) {
        int e = i - NN;
        int d = edst[e];
        int p = atomicAdd(&g_cursor[d], 1);
        g_csrc[p] = esrc[e];
    }
}

// ---------------------------------------------------------------------------
// Fragment-ordered B precompute (k-permuted for float4 A loads):
// For (c, nb, hl, lane, w): n = nb*8 + (lane>>2),
//   logical k = c*16 + (lane&3)*4 + w*2   (elements k, k+1)
// packed bf16x2 of W[k][n], W[k+1][n] (hi: truncated; lo: rn of residual).
// ---------------------------------------------------------------------------
__device__ __forceinline__ uint32_t packpair(float w0, float w1, int hl) {
    uint32_t u0 = __float_as_uint(w0), u1 = __float_as_uint(w1);
    if (hl == 0) return (u0 >> 16) | (u1 & 0xffff0000u);
    float l0 = w0 - __uint_as_float(u0 & 0xffff0000u);
    float l1 = w1 - __uint_as_float(u1 & 0xffff0000u);
    __nv_bfloat162 lb = __floats2bfloat162_rn(l0, l1);
    return *reinterpret_cast<uint32_t*>(&lb);
}

__global__ void k_wfrag(const float* __restrict__ W1,
                        const float* __restrict__ W2,
                        const float* __restrict__ W3) {
    int i = blockIdx.x * blockDim.x + threadIdx.x;
    const float* W; uint32_t* out; int M, NB, rel;
    if (i < 16384)              { W = W1; out = g_bf1; M = 64;  NB = 8;  rel = i; }
    else if (i < 16384 + 20480) { W = W2; out = g_bf2; M = 64;  NB = 8;  rel = i - 16384; }
    else if (i < 45056)         { W = W3; out = g_bf3; M = 128; NB = 16; rel = i - 36864; }
    else return;
    int w    = rel & 1;
    int lane = (rel >> 1) & 31;
    int hl   = (rel >> 6) & 1;
    int nb   = (rel >> 7) % NB;
    int c    = rel / (NB * 128);
    int g = lane >> 2, tg = lane & 3;
    int n = nb * 8 + g;
    int k = c * 16 + tg * 4 + w * 2;   // k-permuted mapping
    out[rel] = packpair(W[k * M + n], W[(k + 1) * M + n], hl);
}

// ---------------------------------------------------------------------------
// mma.sync bf16 GEMM, 3-term split, M=32/warp (2 m-tiles), 256-thr CTA,
// __launch_bounds__(256,2). A: one LDG.128 per row per chunk (k-permuted
// fragment layout; B precompute carries the matching permutation).
// B: fragment-ordered coalesced LDG.64s (L1/L2-resident).
// Output: h16 (fp16) + fused attention dots a_src/a_dst (fp32 from accs).
// ---------------------------------------------------------------------------
#define MMA_BF16(c, a, b)                                                     \
    asm volatile(                                                             \
        "mma.sync.aligned.m16n8k16.row.col.f32.bf16.bf16.f32 "                \
        "{%0,%1,%2,%3}, {%4,%5,%6,%7}, {%8,%9}, {%0,%1,%2,%3};"               \
        : "+f"((c)[0]), "+f"((c)[1]), "+f"((c)[2]), "+f"((c)[3])              \
        : "r"((a)[0]), "r"((a)[1]), "r"((a)[2]), "r"((a)[3]),                 \
          "r"((b)[0]), "r"((b)[1]))

__device__ __forceinline__ void split2(float2 f, uint32_t& hi, uint32_t& lo) {
    uint32_t u0 = __float_as_uint(f.x), u1 = __float_as_uint(f.y);
    hi = (u0 >> 16) | (u1 & 0xffff0000u);  // packed bf16x2 (truncated)
    float l0 = f.x - __uint_as_float(u0 & 0xffff0000u);
    float l1 = f.y - __uint_as_float(u1 & 0xffff0000u);
    __nv_bfloat162 lb = __floats2bfloat162_rn(l0, l1);
    lo = *reinterpret_cast<uint32_t*>(&lb);
}

template <int CH, int HROW, int NBT>
__global__ __launch_bounds__(256, 2) void k_gemm_mma(
    const float* __restrict__ A1, int K1,
    const float* __restrict__ A2, int K2,
    const uint32_t* __restrict__ Bf,
    const float* __restrict__ ats,
    const float* __restrict__ atd)
{
    int tid = threadIdx.x;
    int wid = tid >> 5, lane = tid & 31;
    int g = lane >> 2, tg = lane & 3;
    int warpRow = blockIdx.x * 256 + wid * 32;
    int colBase = blockIdx.y * 64;
    int nbBase = blockIdx.y * 8;
    int Ktot = K1 + K2;
    int nch = Ktot >> 4;

    float acc[2][8][4];
#pragma unroll
    for (int mt = 0; mt < 2; mt++)
#pragma unroll
        for (int nb = 0; nb < 8; nb++)
#pragma unroll
            for (int j = 0; j < 4; j++) acc[mt][nb][j] = 0.f;

    for (int c = 0; c < nch; c++) {
        int kbase = c << 4;
        const float* src; int stride, koff;
        if (kbase < K1) { src = A1; stride = K1; koff = kbase; }
        else            { src = A2; stride = K2; koff = kbase - K1; }

        // B fragments: coalesced LDG.64 per (nb, hi/lo)
        uint32_t bh[8][2], bl[8][2];
        const uint32_t* bp = Bf + ((size_t)(c * NBT + nbBase) * 2) * 64 + lane * 2;
#pragma unroll
        for (int nb = 0; nb < 8; nb++) {
            uint2 h2 = *(const uint2*)(bp + nb * 128);
            uint2 l2 = *(const uint2*)(bp + nb * 128 + 64);
            bh[nb][0] = h2.x; bh[nb][1] = h2.y;
            bl[nb][0] = l2.x; bl[nb][1] = l2.y;
        }

#pragma unroll
        for (int mt = 0; mt < 2; mt++) {
            int r0 = warpRow + mt * 16 + g;
            int r1 = r0 + 8;
            if (r0 >= NN) r0 = NN - 1;
            if (r1 >= NN) r1 = NN - 1;
            // one LDG.128 per row: lane tg holds logical k = 4tg..4tg+3
            float4 q0 = *(const float4*)(src + (size_t)r0 * stride + koff + tg * 4);
            float4 q1 = *(const float4*)(src + (size_t)r1 * stride + koff + tg * 4);
            uint32_t ah[4], al[4];
            split2(make_float2(q0.x, q0.y), ah[0], al[0]);  // frag slot (r0, b0)
            split2(make_float2(q1.x, q1.y), ah[1], al[1]);  // frag slot (r1, b0)
            split2(make_float2(q0.z, q0.w), ah[2], al[2]);  // frag slot (r0, b1)
            split2(make_float2(q1.z, q1.w), ah[3], al[3]);  // frag slot (r1, b1)
#pragma unroll
            for (int nb = 0; nb < 8; nb++) {
                MMA_BF16(acc[mt][nb], ah, bh[nb]);
                MMA_BF16(acc[mt][nb], ah, bl[nb]);
                MMA_BF16(acc[mt][nb], al, bh[nb]);
            }
        }
    }

    // att weights for this lane's columns: ats/atd laid out so index == col
    float ws[8][2], wd[8][2];
#pragma unroll
    for (int nb = 0; nb < 8; nb++) {
        int col = colBase + nb * 8 + tg * 2;
        float2 a = *(const float2*)(ats + col);
        float2 b = *(const float2*)(atd + col);
        ws[nb][0] = a.x; ws[nb][1] = a.y;
        wd[nb][0] = b.x; wd[nb][1] = b.y;
    }

#pragma unroll
    for (int mt = 0; mt < 2; mt++) {
        int r0 = warpRow + mt * 16 + g;
        int r1 = r0 + 8;
        // emit h16
#pragma unroll
        for (int nb = 0; nb < 8; nb++) {
            int col = colBase + nb * 8 + tg * 2;
            if (r0 < NN)
                *(__half2*)(g_h16 + (size_t)r0 * HROW + col) =
                    __floats2half2_rn(acc[mt][nb][0], acc[mt][nb][1]);
            if (r1 < NN)
                *(__half2*)(g_h16 + (size_t)r1 * HROW + col) =
                    __floats2half2_rn(acc[mt][nb][2], acc[mt][nb][3]);
        }
        // fused attention dots: per-head partials, reduced over tg lanes
        float s0[8], d0[8], s1[8], d1[8];
#pragma unroll
        for (int nb = 0; nb < 8; nb++) {
            s0[nb] = acc[mt][nb][0] * ws[nb][0] + acc[mt][nb][1] * ws[nb][1];
            d0[nb] = acc[mt][nb][0] * wd[nb][0] + acc[mt][nb][1] * wd[nb][1];
            s1[nb] = acc[mt][nb][2] * ws[nb][0] + acc[mt][nb][3] * ws[nb][1];
            d1[nb] = acc[mt][nb][2] * wd[nb][0] + acc[mt][nb][3] * wd[nb][1];
        }
        if (CH == 8) {
            // head == nb
#pragma unroll
            for (int nb = 0; nb < 8; nb++) {
#pragma unroll
                for (int dlt = 1; dlt <= 2; dlt <<= 1) {
                    s0[nb] += __shfl_xor_sync(0xffffffffu, s0[nb], dlt);
                    d0[nb] += __shfl_xor_sync(0xffffffffu, d0[nb], dlt);
                    s1[nb] += __shfl_xor_sync(0xffffffffu, s1[nb], dlt);
                    d1[nb] += __shfl_xor_sync(0xffffffffu, d1[nb], dlt);
                }
            }
            if (r0 < NN) {
                g_asrc[r0 * 8 + tg]     = s0[tg];
                g_asrc[r0 * 8 + tg + 4] = s0[tg + 4];
                g_adst[r0 * 8 + tg]     = d0[tg];
                g_adst[r0 * 8 + tg + 4] = d0[tg + 4];
            }
            if (r1 < NN) {
                g_asrc[r1 * 8 + tg]     = s1[tg];
                g_asrc[r1 * 8 + tg + 4] = s1[tg + 4];
                g_adst[r1 * 8 + tg]     = d1[tg];
                g_adst[r1 * 8 + tg + 4] = d1[tg + 4];
            }
        } else {
            // CH == 16: head spans 2 nb; 4 heads per 64-col block
            int headBase = colBase >> 4;
            float hs0[4], hd0[4], hs1[4], hd1[4];
#pragma unroll
            for (int hh = 0; hh < 4; hh++) {
                hs0[hh] = s0[2 * hh] + s0[2 * hh + 1];
                hd0[hh] = d0[2 * hh] + d0[2 * hh + 1];
                hs1[hh] = s1[2 * hh] + s1[2 * hh + 1];
                hd1[hh] = d1[2 * hh] + d1[2 * hh + 1];
#pragma unroll
                for (int dlt = 1; dlt <= 2; dlt <<= 1) {
                    hs0[hh] += __shfl_xor_sync(0xffffffffu, hs0[hh], dlt);
                    hd0[hh] += __shfl_xor_sync(0xffffffffu, hd0[hh], dlt);
                    hs1[hh] += __shfl_xor_sync(0xffffffffu, hs1[hh], dlt);
                    hd1[hh] += __shfl_xor_sync(0xffffffffu, hd1[hh], dlt);
                }
            }
            if (r0 < NN) {
                g_asrc[r0 * 8 + headBase + tg] = hs0[tg];
                g_adst[r0 * 8 + headBase + tg] = hd0[tg];
            }
            if (r1 < NN) {
                g_asrc[r1 * 8 + headBase + tg] = hs1[tg];
                g_adst[r1 * 8 + headBase + tg] = hd1[tg];
            }
        }
    }
}

// ---------------------------------------------------------------------------
// Aggregation, ONE-PASS softmax (logits clamped at 70), fp16 h gather.
// One warp per dst node; 2-edge pipeline.
// FINAL: head-mean + bias + log_softmax fused.
// ---------------------------------------------------------------------------
template <int C, bool FINAL>
__global__ __launch_bounds__(256) void k_agg(
    const __half* __restrict__ h16,
    const float* __restrict__ bias,
    const float* __restrict__ prelu_a,
    float* __restrict__ out)
{
    constexpr int VEC = C / 4;
    constexpr int HROW = C * 8;
    int warp = (blockIdx.x * blockDim.x + threadIdx.x) >> 5;
    if (warp >= NN) return;
    int lane = threadIdx.x & 31;
    int head = lane >> 2;

    int beg = g_rowptr[warp];
    int end = g_rowptr[warp + 1];
    float ad = g_adst[warp * 8 + head];

    float ssum = 0.f;
    float acc[VEC];
#pragma unroll
    for (int j = 0; j < VEC; j++) acc[j] = 0.f;

    int i = beg;
    for (; i + 2 <= end; i += 2) {
        int s0 = g_csrc[i];
        int s1 = g_csrc[i + 1];
        float a0 = g_asrc[s0 * 8 + head];
        float a1 = g_asrc[s1 * 8 + head];
        float e0 = a0 + ad; e0 = (e0 < 0.f) ? 0.2f * e0 : e0;
        float e1 = a1 + ad; e1 = (e1 < 0.f) ? 0.2f * e1 : e1;
        float w0 = __expf(fminf(e0, 70.f));
        float w1 = __expf(fminf(e1, 70.f));
        ssum += w0 + w1;
        if (!FINAL) {
            uint32_t u0 = *(const uint32_t*)(h16 + (size_t)s0 * HROW + lane * 2);
            uint32_t u1 = *(const uint32_t*)(h16 + (size_t)s1 * HROW + lane * 2);
            float2 p0 = __half22float2(*(__half2*)&u0);
            float2 p1 = __half22float2(*(__half2*)&u1);
            acc[0] += w0 * p0.x + w1 * p1.x;
            acc[1] += w0 * p0.y + w1 * p1.y;
        } else {
            uint2 u0 = *(const uint2*)(h16 + (size_t)s0 * HROW + lane * 4);
            uint2 u1 = *(const uint2*)(h16 + (size_t)s1 * HROW + lane * 4);
            float2 p00 = __half22float2(*(__half2*)&u0.x);
            float2 p01 = __half22float2(*(__half2*)&u0.y);
            float2 p10 = __half22float2(*(__half2*)&u1.x);
            float2 p11 = __half22float2(*(__half2*)&u1.y);
            acc[0] += w0 * p00.x + w1 * p10.x;
            acc[1] += w0 * p00.y + w1 * p10.y;
            acc[2] += w0 * p01.x + w1 * p11.x;
            acc[3] += w0 * p01.y + w1 * p11.y;
        }
    }
    if (i < end) {
        int s0 = g_csrc[i];
        float a0 = g_asrc[s0 * 8 + head];
        float e0 = a0 + ad; e0 = (e0 < 0.f) ? 0.2f * e0 : e0;
        float w0 = __expf(fminf(e0, 70.f));
        ssum += w0;
        if (!FINAL) {
            uint32_t u0 = *(const uint32_t*)(h16 + (size_t)s0 * HROW + lane * 2);
            float2 p0 = __half22float2(*(__half2*)&u0);
            acc[0] += w0 * p0.x;
            acc[1] += w0 * p0.y;
        } else {
            uint2 u0 = *(const uint2*)(h16 + (size_t)s0 * HROW + lane * 4);
            float2 p00 = __half22float2(*(__half2*)&u0.x);
            float2 p01 = __half22float2(*(__half2*)&u0.y);
            acc[0] += w0 * p00.x;
            acc[1] += w0 * p00.y;
            acc[2] += w0 * p01.x;
            acc[3] += w0 * p01.y;
        }
    }
    float inv = 1.f / (ssum + 1e-16f);

    if (!FINAL) {
        float p = prelu_a[0];
        float v[VEC];
#pragma unroll
        for (int j = 0; j < VEC; j++) {
            float t = acc[j] * inv + bias[lane * VEC + j];
            v[j] = (t >= 0.f) ? t : p * t;
        }
        float2 f = make_float2(v[0], v[1]);
        *(float2*)(out + (size_t)warp * 64 + lane * 2) = f;
    } else {
        // mean over heads (lanes stride 4), + bias, log_softmax over 16 ch
        float v[4];
#pragma unroll
        for (int j = 0; j < 4; j++) v[j] = acc[j] * inv;
#pragma unroll
        for (int j = 0; j < 4; j++) {
            v[j] += __shfl_xor_sync(0xffffffffu, v[j], 4);
            v[j] += __shfl_xor_sync(0xffffffffu, v[j], 8);
            v[j] += __shfl_xor_sync(0xffffffffu, v[j], 16);
            v[j] = v[j] * 0.125f + bias[(lane & 3) * 4 + j];
        }
        float mx = fmaxf(fmaxf(v[0], v[1]), fmaxf(v[2], v[3]));
        mx = fmaxf(mx, __shfl_xor_sync(0xffffffffu, mx, 1));
        mx = fmaxf(mx, __shfl_xor_sync(0xffffffffu, mx, 2));
        float se = 0.f;
#pragma unroll
        for (int j = 0; j < 4; j++) se += __expf(v[j] - mx);
        se += __shfl_xor_sync(0xffffffffu, se, 1);
        se += __shfl_xor_sync(0xffffffffu, se, 2);
        float lse = mx + __logf(se);
        if (lane < 4) {
            float4 f = make_float4(v[0] - lse, v[1] - lse, v[2] - lse, v[3] - lse);
            *(float4*)(out + (size_t)warp * 16 + lane * 4) = f;
        }
    }
}

// ---------------------------------------------------------------------------
// Launch
// ---------------------------------------------------------------------------
extern "C" void kernel_launch(void* const* d_in, const int* in_sizes, int n_in,
                              void* d_out, int out_size)
{
    const float* x   = (const float*)d_in[0];
    const int*   ei  = (const int*)d_in[1];
    const float* W1  = (const float*)d_in[2];
    const float* as1 = (const float*)d_in[3];
    const float* ad1 = (const float*)d_in[4];
    const float* b1  = (const float*)d_in[5];
    const float* W2  = (const float*)d_in[6];
    const float* as2 = (const float*)d_in[7];
    const float* ad2 = (const float*)d_in[8];
    const float* b2  = (const float*)d_in[9];
    const float* W3  = (const float*)d_in[10];
    const float* as3 = (const float*)d_in[11];
    const float* ad3 = (const float*)d_in[12];
    const float* b3  = (const float*)d_in[13];
    const float* p1  = (const float*)d_in[14];
    const float* p2  = (const float*)d_in[15];
    float* out = (float*)d_out;

    void *po, *ph16, *pb1, *pb2, *pb3;
    cudaGetSymbolAddress(&po, g_out);
    cudaGetSymbolAddress(&ph16, g_h16);
    cudaGetSymbolAddress(&pb1, g_bf1);
    cudaGetSymbolAddress(&pb2, g_bf2);
    cudaGetSymbolAddress(&pb3, g_bf3);
    float* o = (float*)po;
    const __half* h16 = (const __half*)ph16;

    const int* esrc = ei;
    const int* edst = ei + NE;

    int agg_blocks = (NN * 32 + 255) / 256;
    dim3 gg1((NN + 255) / 256, 1);   // 391 CTAs of 256 threads
    dim3 gg3((NN + 255) / 256, 2);

    // Launch order puts gemm1 at position 4 (ncu -s 5 -c 1 capture window).
    k_deg_init<<<(NN + 255) / 256, 256>>>();                              // 1
    k_hist<<<(NE + 255) / 256, 256>>>(edst);                              // 2
    k_wfrag<<<(45056 + 255) / 256, 256>>>(W1, W2, W3);                    // 3

    // Layer-1 GEMM (independent of CSR)
    k_gemm_mma<8, 64, 8><<<gg1, 256>>>(x, 256, (const float*)0, 0,        // 4
                                       (const uint32_t*)pb1, as1, ad1);

    // CSR scan + scatter (coalesced two-level scan)
    k_scan_a<<<SCAN_TILES, SCAN_T>>>();                                   // 5
    k_scan_b<<<1, 256>>>();                                               // 6
    k_scan_c<<<SCAN_TILES, SCAN_T>>>();                                   // 7
    k_scatter<<<(NN + NE + 255) / 256, 256>>>(esrc, edst);                // 8

    // Layer 1 aggregate ; +b1 ; PReLU(p1)
    k_agg<8, false><<<agg_blocks, 256>>>(h16, b1, p1, o);                 // 9

    // Layer 2
    k_gemm_mma<8, 64, 8><<<gg1, 256>>>(x, 256, o, 64,
                                       (const uint32_t*)pb2, as2, ad2);
    k_agg<8, false><<<agg_blocks, 256>>>(h16, b2, p2, o);

    // Layer 3
    k_gemm_mma<16, 128, 16><<<gg3, 256>>>(o, 64, (const float*)0, 0,
                                          (const uint32_t*)pb3, as3, ad3);
    k_agg<16, true><<<agg_blocks, 256>>>(h16, b3, (const float*)0, out);
}

// round 16
// speedup vs baseline: 1.8029x; 1.0327x over previous
#include <cuda_runtime.h>
#include <cuda_fp16.h>
#include <cuda_bf16.h>
#include <stdint.h>

// Problem constants
#define NN 100000
#define NE 1600000
#define NE2 (NE + NN)
#define SCAN_T 512
#define SCAN_TILES ((NN + SCAN_T - 1) / SCAN_T)  // 196

// ---------------------------------------------------------------------------
// Scratch (device globals — no allocation allowed)
// ---------------------------------------------------------------------------
__device__ __half g_h16[(size_t)NN * 128]; // fp16 linear output (all layers)
__device__ float  g_out[(size_t)NN * 64];  // per-layer aggregated output
__device__ float  g_asrc[NN * 8];
__device__ float  g_adst[NN * 8];
__device__ int    g_rowptr[NN + 1];
__device__ int    g_cursor[NN];
__device__ int    g_csrc[NE2];
__device__ int    g_cnt[NN];
__device__ int    g_tilesum[SCAN_TILES];
__device__ int    g_tileoff[SCAN_TILES];
// Fragment-ordered B (bf16 hi/lo split), word layout:
//   idx = (((c*NB + nb)*2 + hl)*32 + lane)*2 + w
// k-PERMUTED to match contiguous float4 A loads: logical k = c*16 + tg*4 + w*2
__device__ uint32_t g_bf1[16 * 8 * 2 * 64];   // K=256: 16 chunks, NB=8
__device__ uint32_t g_bf2[20 * 8 * 2 * 64];   // K=320: 20 chunks, NB=8
__device__ uint32_t g_bf3[4 * 16 * 2 * 64];   // K=64:   4 chunks, NB=16

// ---------------------------------------------------------------------------
// CSR build (dst-sorted adjacency incl. self-loops), reused for all 3 layers
// ---------------------------------------------------------------------------
__global__ void k_deg_init() {
    int i = blockIdx.x * blockDim.x + threadIdx.x;
    if (i < NN) g_cnt[i] = 1;  // self loop
}

__global__ void k_hist(const int* __restrict__ edst) {
    int e = blockIdx.x * blockDim.x + threadIdx.x;
    if (e < NE) atomicAdd(&g_cnt[edst[e]], 1);
}

// Coalesced two-level scan: tile reduce -> scan tile sums -> tile-local scan
__global__ __launch_bounds__(SCAN_T) void k_scan_a() {
    __shared__ int sm[SCAN_T];
    int i = blockIdx.x * SCAN_T + threadIdx.x;
    sm[threadIdx.x] = (i < NN) ? g_cnt[i] : 0;
    __syncthreads();
#pragma unroll
    for (int off = SCAN_T / 2; off > 0; off >>= 1) {
        if (threadIdx.x < off) sm[threadIdx.x] += sm[threadIdx.x + off];
        __syncthreads();
    }
    if (threadIdx.x == 0) g_tilesum[blockIdx.x] = sm[0];
}

__global__ __launch_bounds__(256) void k_scan_b() {
    __shared__ int sm[256];
    int t = threadIdx.x;
    int v = (t < SCAN_TILES) ? g_tilesum[t] : 0;
    sm[t] = v;
    __syncthreads();
#pragma unroll
    for (int off = 1; off < 256; off <<= 1) {
        int u = (t >= off) ? sm[t - off] : 0;
        __syncthreads();
        sm[t] += u;
        __syncthreads();
    }
    if (t < SCAN_TILES) g_tileoff[t] = sm[t] - v;  // exclusive prefix of tiles
    if (t == 255) g_rowptr[NN] = sm[255];
}

__global__ __launch_bounds__(SCAN_T) void k_scan_c() {
    __shared__ int sm[SCAN_T];
    int i = blockIdx.x * SCAN_T + threadIdx.x;
    int v = (i < NN) ? g_cnt[i] : 0;
    sm[threadIdx.x] = v;
    __syncthreads();
#pragma unroll
    for (int off = 1; off < SCAN_T; off <<= 1) {
        int u = (threadIdx.x >= off) ? sm[threadIdx.x - off] : 0;
        __syncthreads();
        sm[threadIdx.x] += u;
        __syncthreads();
    }
    if (i < NN) {
        int ex = g_tileoff[blockIdx.x] + sm[threadIdx.x] - v;  // exclusive
        g_rowptr[i] = ex;
        g_cursor[i] = ex;
    }
}

__global__ void k_scatter(const int* __restrict__ esrc, const int* __restrict__ edst) {
    int i = blockIdx.x * blockDim.x + threadIdx.x;
    if (i < NN) {
        int p = atomicAdd(&g_cursor[i], 1);
        g_csrc[p] = i;  // self loop
    } else if (i < NN + NE) {
        int e = i - NN;
        int d = edst[e];
        int p = atomicAdd(&g_cursor[d], 1);
        g_csrc[p] = esrc[e];
    }
}

// ---------------------------------------------------------------------------
// Fragment-ordered B precompute (k-permuted for float4 A loads):
// For (c, nb, hl, lane, w): n = nb*8 + (lane>>2),
//   logical k = c*16 + (lane&3)*4 + w*2   (elements k, k+1)
// packed bf16x2 of W[k][n], W[k+1][n] (hi: truncated; lo: rn of residual).
// ---------------------------------------------------------------------------
__device__ __forceinline__ uint32_t packpair(float w0, float w1, int hl) {
    uint32_t u0 = __float_as_uint(w0), u1 = __float_as_uint(w1);
    if (hl == 0) return (u0 >> 16) | (u1 & 0xffff0000u);
    float l0 = w0 - __uint_as_float(u0 & 0xffff0000u);
    float l1 = w1 - __uint_as_float(u1 & 0xffff0000u);
    __nv_bfloat162 lb = __floats2bfloat162_rn(l0, l1);
    return *reinterpret_cast<uint32_t*>(&lb);
}

__global__ void k_wfrag(const float* __restrict__ W1,
                        const float* __restrict__ W2,
                        const float* __restrict__ W3) {
    int i = blockIdx.x * blockDim.x + threadIdx.x;
    const float* W; uint32_t* out; int M, NB, rel;
    if (i < 16384)              { W = W1; out = g_bf1; M = 64;  NB = 8;  rel = i; }
    else if (i < 16384 + 20480) { W = W2; out = g_bf2; M = 64;  NB = 8;  rel = i - 16384; }
    else if (i < 45056)         { W = W3; out = g_bf3; M = 128; NB = 16; rel = i - 36864; }
    else return;
    int w    = rel & 1;
    int lane = (rel >> 1) & 31;
    int hl   = (rel >> 6) & 1;
    int nb   = (rel >> 7) % NB;
    int c    = rel / (NB * 128);
    int g = lane >> 2, tg = lane & 3;
    int n = nb * 8 + g;
    int k = c * 16 + tg * 4 + w * 2;   // k-permuted mapping
    out[rel] = packpair(W[k * M + n], W[(k + 1) * M + n], hl);
}

// ---------------------------------------------------------------------------
// mma.sync bf16 GEMM, 3-term split, M=32/warp (2 m-tiles), 256-thr CTA,
// __launch_bounds__(256,2). A: one LDG.128 per row per chunk (k-permuted
// fragment layout; B precompute carries the matching permutation).
// B: fragment-ordered coalesced LDG.64s (L1/L2-resident).
// Output: h16 (fp16) + fused attention dots a_src/a_dst (fp32 from accs).
// ---------------------------------------------------------------------------
#define MMA_BF16(c, a, b)                                                     \
    asm volatile(                                                             \
        "mma.sync.aligned.m16n8k16.row.col.f32.bf16.bf16.f32 "                \
        "{%0,%1,%2,%3}, {%4,%5,%6,%7}, {%8,%9}, {%0,%1,%2,%3};"               \
        : "+f"((c)[0]), "+f"((c)[1]), "+f"((c)[2]), "+f"((c)[3])              \
        : "r"((a)[0]), "r"((a)[1]), "r"((a)[2]), "r"((a)[3]),                 \
          "r"((b)[0]), "r"((b)[1]))

__device__ __forceinline__ void split2(float2 f, uint32_t& hi, uint32_t& lo) {
    uint32_t u0 = __float_as_uint(f.x), u1 = __float_as_uint(f.y);
    hi = (u0 >> 16) | (u1 & 0xffff0000u);  // packed bf16x2 (truncated)
    float l0 = f.x - __uint_as_float(u0 & 0xffff0000u);
    float l1 = f.y - __uint_as_float(u1 & 0xffff0000u);
    __nv_bfloat162 lb = __floats2bfloat162_rn(l0, l1);
    lo = *reinterpret_cast<uint32_t*>(&lb);
}

template <int CH, int HROW, int NBT>
__global__ __launch_bounds__(256, 2) void k_gemm_mma(
    const float* __restrict__ A1, int K1,
    const float* __restrict__ A2, int K2,
    const uint32_t* __restrict__ Bf,
    const float* __restrict__ ats,
    const float* __restrict__ atd)
{
    int tid = threadIdx.x;
    int wid = tid >> 5, lane = tid & 31;
    int g = lane >> 2, tg = lane & 3;
    int warpRow = blockIdx.x * 256 + wid * 32;
    int colBase = blockIdx.y * 64;
    int nbBase = blockIdx.y * 8;
    int Ktot = K1 + K2;
    int nch = Ktot >> 4;

    float acc[2][8][4];
#pragma unroll
    for (int mt = 0; mt < 2; mt++)
#pragma unroll
        for (int nb = 0; nb < 8; nb++)
#pragma unroll
            for (int j = 0; j < 4; j++) acc[mt][nb][j] = 0.f;

    for (int c = 0; c < nch; c++) {
        int kbase = c << 4;
        const float* src; int stride, koff;
        if (kbase < K1) { src = A1; stride = K1; koff = kbase; }
        else            { src = A2; stride = K2; koff = kbase - K1; }

        // B fragments: coalesced LDG.64 per (nb, hi/lo)
        uint32_t bh[8][2], bl[8][2];
        const uint32_t* bp = Bf + ((size_t)(c * NBT + nbBase) * 2) * 64 + lane * 2;
#pragma unroll
        for (int nb = 0; nb < 8; nb++) {
            uint2 h2 = *(const uint2*)(bp + nb * 128);
            uint2 l2 = *(const uint2*)(bp + nb * 128 + 64);
            bh[nb][0] = h2.x; bh[nb][1] = h2.y;
            bl[nb][0] = l2.x; bl[nb][1] = l2.y;
        }

#pragma unroll
        for (int mt = 0; mt < 2; mt++) {
            int r0 = warpRow + mt * 16 + g;
            int r1 = r0 + 8;
            if (r0 >= NN) r0 = NN - 1;
            if (r1 >= NN) r1 = NN - 1;
            // one LDG.128 per row: lane tg holds logical k = 4tg..4tg+3
            float4 q0 = *(const float4*)(src + (size_t)r0 * stride + koff + tg * 4);
            float4 q1 = *(const float4*)(src + (size_t)r1 * stride + koff + tg * 4);
            uint32_t ah[4], al[4];
            split2(make_float2(q0.x, q0.y), ah[0], al[0]);  // frag slot (r0, b0)
            split2(make_float2(q1.x, q1.y), ah[1], al[1]);  // frag slot (r1, b0)
            split2(make_float2(q0.z, q0.w), ah[2], al[2]);  // frag slot (r0, b1)
            split2(make_float2(q1.z, q1.w), ah[3], al[3]);  // frag slot (r1, b1)
#pragma unroll
            for (int nb = 0; nb < 8; nb++) {
                MMA_BF16(acc[mt][nb], ah, bh[nb]);
                MMA_BF16(acc[mt][nb], ah, bl[nb]);
                MMA_BF16(acc[mt][nb], al, bh[nb]);
            }
        }
    }

    // att weights for this lane's columns: ats/atd laid out so index == col
    float ws[8][2], wd[8][2];
#pragma unroll
    for (int nb = 0; nb < 8; nb++) {
        int col = colBase + nb * 8 + tg * 2;
        float2 a = *(const float2*)(ats + col);
        float2 b = *(const float2*)(atd + col);
        ws[nb][0] = a.x; ws[nb][1] = a.y;
        wd[nb][0] = b.x; wd[nb][1] = b.y;
    }

#pragma unroll
    for (int mt = 0; mt < 2; mt++) {
        int r0 = warpRow + mt * 16 + g;
        int r1 = r0 + 8;
        // emit h16
#pragma unroll
        for (int nb = 0; nb < 8; nb++) {
            int col = colBase + nb * 8 + tg * 2;
            if (r0 < NN)
                *(__half2*)(g_h16 + (size_t)r0 * HROW + col) =
                    __floats2half2_rn(acc[mt][nb][0], acc[mt][nb][1]);
            if (r1 < NN)
                *(__half2*)(g_h16 + (size_t)r1 * HROW + col) =
                    __floats2half2_rn(acc[mt][nb][2], acc[mt][nb][3]);
        }
        // fused attention dots: per-head partials, reduced over tg lanes
        float s0[8], d0[8], s1[8], d1[8];
#pragma unroll
        for (int nb = 0; nb < 8; nb++) {
            s0[nb] = acc[mt][nb][0] * ws[nb][0] + acc[mt][nb][1] * ws[nb][1];
            d0[nb] = acc[mt][nb][0] * wd[nb][0] + acc[mt][nb][1] * wd[nb][1];
            s1[nb] = acc[mt][nb][2] * ws[nb][0] + acc[mt][nb][3] * ws[nb][1];
            d1[nb] = acc[mt][nb][2] * wd[nb][0] + acc[mt][nb][3] * wd[nb][1];
        }
        if (CH == 8) {
            // head == nb
#pragma unroll
            for (int nb = 0; nb < 8; nb++) {
#pragma unroll
                for (int dlt = 1; dlt <= 2; dlt <<= 1) {
                    s0[nb] += __shfl_xor_sync(0xffffffffu, s0[nb], dlt);
                    d0[nb] += __shfl_xor_sync(0xffffffffu, d0[nb], dlt);
                    s1[nb] += __shfl_xor_sync(0xffffffffu, s1[nb], dlt);
                    d1[nb] += __shfl_xor_sync(0xffffffffu, d1[nb], dlt);
                }
            }
            if (r0 < NN) {
                g_asrc[r0 * 8 + tg]     = s0[tg];
                g_asrc[r0 * 8 + tg + 4] = s0[tg + 4];
                g_adst[r0 * 8 + tg]     = d0[tg];
                g_adst[r0 * 8 + tg + 4] = d0[tg + 4];
            }
            if (r1 < NN) {
                g_asrc[r1 * 8 + tg]     = s1[tg];
                g_asrc[r1 * 8 + tg + 4] = s1[tg + 4];
                g_adst[r1 * 8 + tg]     = d1[tg];
                g_adst[r1 * 8 + tg + 4] = d1[tg + 4];
            }
        } else {
            // CH == 16: head spans 2 nb; 4 heads per 64-col block
            int headBase = colBase >> 4;
            float hs0[4], hd0[4], hs1[4], hd1[4];
#pragma unroll
            for (int hh = 0; hh < 4; hh++) {
                hs0[hh] = s0[2 * hh] + s0[2 * hh + 1];
                hd0[hh] = d0[2 * hh] + d0[2 * hh + 1];
                hs1[hh] = s1[2 * hh] + s1[2 * hh + 1];
                hd1[hh] = d1[2 * hh] + d1[2 * hh + 1];
#pragma unroll
                for (int dlt = 1; dlt <= 2; dlt <<= 1) {
                    hs0[hh] += __shfl_xor_sync(0xffffffffu, hs0[hh], dlt);
                    hd0[hh] += __shfl_xor_sync(0xffffffffu, hd0[hh], dlt);
                    hs1[hh] += __shfl_xor_sync(0xffffffffu, hs1[hh], dlt);
                    hd1[hh] += __shfl_xor_sync(0xffffffffu, hd1[hh], dlt);
                }
            }
            if (r0 < NN) {
                g_asrc[r0 * 8 + headBase + tg] = hs0[tg];
                g_adst[r0 * 8 + headBase + tg] = hd0[tg];
            }
            if (r1 < NN) {
                g_asrc[r1 * 8 + headBase + tg] = hs1[tg];
                g_adst[r1 * 8 + headBase + tg] = hd1[tg];
            }
        }
    }
}

// ---------------------------------------------------------------------------
// Aggregation, ONE-PASS softmax (logits clamped at 70), fp16 h gather.
// One warp per dst node; 4-edge software pipeline (batched phase-ordered
// loads: csrc x4 -> asrc x4 + h16 x4 -> compute).
// FINAL: head-mean + bias + log_softmax fused.
// ---------------------------------------------------------------------------
template <int C, bool FINAL>
__global__ __launch_bounds__(256) void k_agg(
    const __half* __restrict__ h16,
    const float* __restrict__ bias,
    const float* __restrict__ prelu_a,
    float* __restrict__ out)
{
    constexpr int VEC = C / 4;
    constexpr int HROW = C * 8;
    int warp = (blockIdx.x * blockDim.x + threadIdx.x) >> 5;
    if (warp >= NN) return;
    int lane = threadIdx.x & 31;
    int head = lane >> 2;

    int beg = g_rowptr[warp];
    int end = g_rowptr[warp + 1];
    float ad = g_adst[warp * 8 + head];

    float ssum = 0.f;
    float acc[VEC];
#pragma unroll
    for (int j = 0; j < VEC; j++) acc[j] = 0.f;

    int i = beg;
    for (; i + 4 <= end; i += 4) {
        // phase 1: indices
        int s[4];
#pragma unroll
        for (int u = 0; u < 4; u++) s[u] = g_csrc[i + u];
        // phase 2: all attention logits + all gathers issued together
        float a[4];
#pragma unroll
        for (int u = 0; u < 4; u++) a[u] = g_asrc[s[u] * 8 + head];
        uint32_t h1[4];  // !FINAL payload
        uint2 h2[4];     // FINAL payload
#pragma unroll
        for (int u = 0; u < 4; u++) {
            if (!FINAL)
                h1[u] = *(const uint32_t*)(h16 + (size_t)s[u] * HROW + lane * 2);
            else
                h2[u] = *(const uint2*)(h16 + (size_t)s[u] * HROW + lane * 4);
        }
        // phase 3: compute
#pragma unroll
        for (int u = 0; u < 4; u++) {
            float e = a[u] + ad;
            e = (e < 0.f) ? 0.2f * e : e;
            float w = __expf(fminf(e, 70.f));
            ssum += w;
            if (!FINAL) {
                float2 p = __half22float2(*(__half2*)&h1[u]);
                acc[0] += w * p.x;
                acc[1] += w * p.y;
            } else {
                float2 pa = __half22float2(*(__half2*)&h2[u].x);
                float2 pb = __half22float2(*(__half2*)&h2[u].y);
                acc[0] += w * pa.x;
                acc[1] += w * pa.y;
                acc[2] += w * pb.x;
                acc[3] += w * pb.y;
            }
        }
    }
    for (; i < end; ++i) {
        int s0 = g_csrc[i];
        float a0 = g_asrc[s0 * 8 + head];
        float e0 = a0 + ad; e0 = (e0 < 0.f) ? 0.2f * e0 : e0;
        float w0 = __expf(fminf(e0, 70.f));
        ssum += w0;
        if (!FINAL) {
            uint32_t u0 = *(const uint32_t*)(h16 + (size_t)s0 * HROW + lane * 2);
            float2 p0 = __half22float2(*(__half2*)&u0);
            acc[0] += w0 * p0.x;
            acc[1] += w0 * p0.y;
        } else {
            uint2 u0 = *(const uint2*)(h16 + (size_t)s0 * HROW + lane * 4);
            float2 p00 = __half22float2(*(__half2*)&u0.x);
            float2 p01 = __half22float2(*(__half2*)&u0.y);
            acc[0] += w0 * p00.x;
            acc[1] += w0 * p00.y;
            acc[2] += w0 * p01.x;
            acc[3] += w0 * p01.y;
        }
    }
    float inv = 1.f / (ssum + 1e-16f);

    if (!FINAL) {
        float p = prelu_a[0];
        float v[VEC];
#pragma unroll
        for (int j = 0; j < VEC; j++) {
            float t = acc[j] * inv + bias[lane * VEC + j];
            v[j] = (t >= 0.f) ? t : p * t;
        }
        float2 f = make_float2(v[0], v[1]);
        *(float2*)(out + (size_t)warp * 64 + lane * 2) = f;
    } else {
        // mean over heads (lanes stride 4), + bias, log_softmax over 16 ch
        float v[4];
#pragma unroll
        for (int j = 0; j < 4; j++) v[j] = acc[j] * inv;
#pragma unroll
        for (int j = 0; j < 4; j++) {
            v[j] += __shfl_xor_sync(0xffffffffu, v[j], 4);
            v[j] += __shfl_xor_sync(0xffffffffu, v[j], 8);
            v[j] += __shfl_xor_sync(0xffffffffu, v[j], 16);
            v[j] = v[j] * 0.125f + bias[(lane & 3) * 4 + j];
        }
        float mx = fmaxf(fmaxf(v[0], v[1]), fmaxf(v[2], v[3]));
        mx = fmaxf(mx, __shfl_xor_sync(0xffffffffu, mx, 1));
        mx = fmaxf(mx, __shfl_xor_sync(0xffffffffu, mx, 2));
        float se = 0.f;
#pragma unroll
        for (int j = 0; j < 4; j++) se += __expf(v[j] - mx);
        se += __shfl_xor_sync(0xffffffffu, se, 1);
        se += __shfl_xor_sync(0xffffffffu, se, 2);
        float lse = mx + __logf(se);
        if (lane < 4) {
            float4 f = make_float4(v[0] - lse, v[1] - lse, v[2] - lse, v[3] - lse);
            *(float4*)(out + (size_t)warp * 16 + lane * 4) = f;
        }
    }
}

// ---------------------------------------------------------------------------
// Launch
// ---------------------------------------------------------------------------
extern "C" void kernel_launch(void* const* d_in, const int* in_sizes, int n_in,
                              void* d_out, int out_size)
{
    const float* x   = (const float*)d_in[0];
    const int*   ei  = (const int*)d_in[1];
    const float* W1  = (const float*)d_in[2];
    const float* as1 = (const float*)d_in[3];
    const float* ad1 = (const float*)d_in[4];
    const float* b1  = (const float*)d_in[5];
    const float* W2  = (const float*)d_in[6];
    const float* as2 = (const float*)d_in[7];
    const float* ad2 = (const float*)d_in[8];
    const float* b2  = (const float*)d_in[9];
    const float* W3  = (const float*)d_in[10];
    const float* as3 = (const float*)d_in[11];
    const float* ad3 = (const float*)d_in[12];
    const float* b3  = (const float*)d_in[13];
    const float* p1  = (const float*)d_in[14];
    const float* p2  = (const float*)d_in[15];
    float* out = (float*)d_out;

    void *po, *ph16, *pb1, *pb2, *pb3;
    cudaGetSymbolAddress(&po, g_out);
    cudaGetSymbolAddress(&ph16, g_h16);
    cudaGetSymbolAddress(&pb1, g_bf1);
    cudaGetSymbolAddress(&pb2, g_bf2);
    cudaGetSymbolAddress(&pb3, g_bf3);
    float* o = (float*)po;
    const __half* h16 = (const __half*)ph16;

    const int* esrc = ei;
    const int* edst = ei + NE;

    int agg_blocks = (NN * 32 + 255) / 256;
    dim3 gg1((NN + 255) / 256, 1);   // 391 CTAs of 256 threads
    dim3 gg3((NN + 255) / 256, 2);

    // Launch order puts gemm1 at position 4 (ncu -s 5 -c 1 capture window).
    k_deg_init<<<(NN + 255) / 256, 256>>>();                              // 1
    k_hist<<<(NE + 255) / 256, 256>>>(edst);                              // 2
    k_wfrag<<<(45056 + 255) / 256, 256>>>(W1, W2, W3);                    // 3

    // Layer-1 GEMM (independent of CSR)
    k_gemm_mma<8, 64, 8><<<gg1, 256>>>(x, 256, (const float*)0, 0,        // 4
                                       (const uint32_t*)pb1, as1, ad1);

    // CSR scan + scatter (coalesced two-level scan)
    k_scan_a<<<SCAN_TILES, SCAN_T>>>();                                   // 5
    k_scan_b<<<1, 256>>>();                                               // 6
    k_scan_c<<<SCAN_TILES, SCAN_T>>>();                                   // 7
    k_scatter<<<(NN + NE + 255) / 256, 256>>>(esrc, edst);                // 8

    // Layer 1 aggregate ; +b1 ; PReLU(p1)
    k_agg<8, false><<<agg_blocks, 256>>>(h16, b1, p1, o);                 // 9

    // Layer 2
    k_gemm_mma<8, 64, 8><<<gg1, 256>>>(x, 256, o, 64,
                                       (const uint32_t*)pb2, as2, ad2);
    k_agg<8, false><<<agg_blocks, 256>>>(h16, b2, p2, o);

    // Layer 3
    k_gemm_mma<16, 128, 16><<<gg3, 256>>>(o, 64, (const float*)0, 0,
                                          (const uint32_t*)pb3, as3, ad3);
    k_agg<16, true><<<agg_blocks, 256>>>(h16, b3, (const float*)0, out);
}

// round 17
// speedup vs baseline: 2.0652x; 1.1455x over previous
#include <cuda_runtime.h>
#include <cuda_fp16.h>
#include <cuda_bf16.h>
#include <stdint.h>

// Problem constants
#define NN 100000
#define NE 1600000
#define NE2 (NE + NN)
#define SCAN_T 512
#define SCAN_TILES ((NN + SCAN_T - 1) / SCAN_T)  // 196

// ---------------------------------------------------------------------------
// Scratch (device globals — no allocation allowed)
// ---------------------------------------------------------------------------
__device__ __half g_h16[(size_t)NN * 128]; // fp16 linear output (all layers)
__device__ float  g_out[(size_t)NN * 64];  // per-layer aggregated output
__device__ float  g_asrc[NN * 8];
__device__ float  g_adst[NN * 8];
__device__ int    g_rowptr[NN + 1];
__device__ int    g_cursor[NN];
__device__ int    g_csrc[NE2];
__device__ int    g_cnt[NN];
__device__ int    g_tilesum[SCAN_TILES];
__device__ int    g_tileoff[SCAN_TILES];
// Fragment-ordered B (bf16 hi/lo split), word layout:
//   idx = (((c*NB + nb)*2 + hl)*32 + lane)*2 + w
// k-PERMUTED to match contiguous float4 A loads: logical k = c*16 + tg*4 + w*2
__device__ uint32_t g_bf1[16 * 8 * 2 * 64];   // K=256: 16 chunks, NB=8
__device__ uint32_t g_bf2[20 * 8 * 2 * 64];   // K=320: 20 chunks, NB=8
__device__ uint32_t g_bf3[4 * 16 * 2 * 64];   // K=64:   4 chunks, NB=16

// ---------------------------------------------------------------------------
// CSR build (dst-sorted adjacency incl. self-loops), reused for all 3 layers
// ---------------------------------------------------------------------------
__global__ void k_deg_init() {
    int i = blockIdx.x * blockDim.x + threadIdx.x;
    if (i < NN) g_cnt[i] = 1;  // self loop
}

__global__ void k_hist(const int* __restrict__ edst) {
    int e = blockIdx.x * blockDim.x + threadIdx.x;
    if (e < NE) atomicAdd(&g_cnt[edst[e]], 1);
}

// Coalesced two-level scan: tile reduce -> scan tile sums -> tile-local scan
__global__ __launch_bounds__(SCAN_T) void k_scan_a() {
    __shared__ int sm[SCAN_T];
    int i = blockIdx.x * SCAN_T + threadIdx.x;
    sm[threadIdx.x] = (i < NN) ? g_cnt[i] : 0;
    __syncthreads();
#pragma unroll
    for (int off = SCAN_T / 2; off > 0; off >>= 1) {
        if (threadIdx.x < off) sm[threadIdx.x] += sm[threadIdx.x + off];
        __syncthreads();
    }
    if (threadIdx.x == 0) g_tilesum[blockIdx.x] = sm[0];
}

__global__ __launch_bounds__(256) void k_scan_b() {
    __shared__ int sm[256];
    int t = threadIdx.x;
    int v = (t < SCAN_TILES) ? g_tilesum[t] : 0;
    sm[t] = v;
    __syncthreads();
#pragma unroll
    for (int off = 1; off < 256; off <<= 1) {
        int u = (t >= off) ? sm[t - off] : 0;
        __syncthreads();
        sm[t] += u;
        __syncthreads();
    }
    if (t < SCAN_TILES) g_tileoff[t] = sm[t] - v;  // exclusive prefix of tiles
    if (t == 255) g_rowptr[NN] = sm[255];
}

__global__ __launch_bounds__(SCAN_T) void k_scan_c() {
    __shared__ int sm[SCAN_T];
    int i = blockIdx.x * SCAN_T + threadIdx.x;
    int v = (i < NN) ? g_cnt[i] : 0;
    sm[threadIdx.x] = v;
    __syncthreads();
#pragma unroll
    for (int off = 1; off < SCAN_T; off <<= 1) {
        int u = (threadIdx.x >= off) ? sm[threadIdx.x - off] : 0;
        __syncthreads();
        sm[threadIdx.x] += u;
        __syncthreads();
    }
    if (i < NN) {
        int ex = g_tileoff[blockIdx.x] + sm[threadIdx.x] - v;  // exclusive
        g_rowptr[i] = ex;
        g_cursor[i] = ex;
    }
}

__global__ void k_scatter(const int* __restrict__ esrc, const int* __restrict__ edst) {
    int i = blockIdx.x * blockDim.x + threadIdx.x;
    if (i < NN) {
        int p = atomicAdd(&g_cursor[i], 1);
        g_csrc[p] = i;  // self loop
    } else if (i < NN + NE) {
        int e = i - NN;
        int d = edst[e];
        int p = atomicAdd(&g_cursor[d], 1);
        g_csrc[p] = esrc[e];
    }
}

// ---------------------------------------------------------------------------
// Fragment-ordered B precompute (k-permuted for float4 A loads):
// For (c, nb, hl, lane, w): n = nb*8 + (lane>>2),
//   logical k = c*16 + (lane&3)*4 + w*2   (elements k, k+1)
// packed bf16x2 of W[k][n], W[k+1][n] (hi: truncated; lo: rn of residual).
// ---------------------------------------------------------------------------
__device__ __forceinline__ uint32_t packpair(float w0, float w1, int hl) {
    uint32_t u0 = __float_as_uint(w0), u1 = __float_as_uint(w1);
    if (hl == 0) return (u0 >> 16) | (u1 & 0xffff0000u);
    float l0 = w0 - __uint_as_float(u0 & 0xffff0000u);
    float l1 = w1 - __uint_as_float(u1 & 0xffff0000u);
    __nv_bfloat162 lb = __floats2bfloat162_rn(l0, l1);
    return *reinterpret_cast<uint32_t*>(&lb);
}

__global__ void k_wfrag(const float* __restrict__ W1,
                        const float* __restrict__ W2,
                        const float* __restrict__ W3) {
    int i = blockIdx.x * blockDim.x + threadIdx.x;
    const float* W; uint32_t* out; int M, NB, rel;
    if (i < 16384)              { W = W1; out = g_bf1; M = 64;  NB = 8;  rel = i; }
    else if (i < 16384 + 20480) { W = W2; out = g_bf2; M = 64;  NB = 8;  rel = i - 16384; }
    else if (i < 45056)         { W = W3; out = g_bf3; M = 128; NB = 16; rel = i - 36864; }
    else return;
    int w    = rel & 1;
    int lane = (rel >> 1) & 31;
    int hl   = (rel >> 6) & 1;
    int nb   = (rel >> 7) % NB;
    int c    = rel / (NB * 128);
    int g = lane >> 2, tg = lane & 3;
    int n = nb * 8 + g;
    int k = c * 16 + tg * 4 + w * 2;   // k-permuted mapping
    out[rel] = packpair(W[k * M + n], W[(k + 1) * M + n], hl);
}

// ---------------------------------------------------------------------------
// mma.sync bf16 GEMM, 3-term split, M=32/warp (2 m-tiles), 256-thr CTA,
// __launch_bounds__(256,2). A: one LDG.128 per row per chunk (k-permuted
// fragment layout; B precompute carries the matching permutation).
// B: fragment-ordered coalesced LDG.64s (L1/L2-resident).
// Output: h16 (fp16) + fused attention dots a_src/a_dst (fp32 from accs).
// ---------------------------------------------------------------------------
#define MMA_BF16(c, a, b)                                                     \
    asm volatile(                                                             \
        "mma.sync.aligned.m16n8k16.row.col.f32.bf16.bf16.f32 "                \
        "{%0,%1,%2,%3}, {%4,%5,%6,%7}, {%8,%9}, {%0,%1,%2,%3};"               \
        : "+f"((c)[0]), "+f"((c)[1]), "+f"((c)[2]), "+f"((c)[3])              \
        : "r"((a)[0]), "r"((a)[1]), "r"((a)[2]), "r"((a)[3]),                 \
          "r"((b)[0]), "r"((b)[1]))

__device__ __forceinline__ void split2(float2 f, uint32_t& hi, uint32_t& lo) {
    uint32_t u0 = __float_as_uint(f.x), u1 = __float_as_uint(f.y);
    hi = (u0 >> 16) | (u1 & 0xffff0000u);  // packed bf16x2 (truncated)
    float l0 = f.x - __uint_as_float(u0 & 0xffff0000u);
    float l1 = f.y - __uint_as_float(u1 & 0xffff0000u);
    __nv_bfloat162 lb = __floats2bfloat162_rn(l0, l1);
    lo = *reinterpret_cast<uint32_t*>(&lb);
}

template <int CH, int HROW, int NBT>
__global__ __launch_bounds__(256, 2) void k_gemm_mma(
    const float* __restrict__ A1, int K1,
    const float* __restrict__ A2, int K2,
    const uint32_t* __restrict__ Bf,
    const float* __restrict__ ats,
    const float* __restrict__ atd)
{
    int tid = threadIdx.x;
    int wid = tid >> 5, lane = tid & 31;
    int g = lane >> 2, tg = lane & 3;
    int warpRow = blockIdx.x * 256 + wid * 32;
    int colBase = blockIdx.y * 64;
    int nbBase = blockIdx.y * 8;
    int Ktot = K1 + K2;
    int nch = Ktot >> 4;

    float acc[2][8][4];
#pragma unroll
    for (int mt = 0; mt < 2; mt++)
#pragma unroll
        for (int nb = 0; nb < 8; nb++)
#pragma unroll
            for (int j = 0; j < 4; j++) acc[mt][nb][j] = 0.f;

    for (int c = 0; c < nch; c++) {
        int kbase = c << 4;
        const float* src; int stride, koff;
        if (kbase < K1) { src = A1; stride = K1; koff = kbase; }
        else            { src = A2; stride = K2; koff = kbase - K1; }

        // B fragments: coalesced LDG.64 per (nb, hi/lo)
        uint32_t bh[8][2], bl[8][2];
        const uint32_t* bp = Bf + ((size_t)(c * NBT + nbBase) * 2) * 64 + lane * 2;
#pragma unroll
        for (int nb = 0; nb < 8; nb++) {
            uint2 h2 = *(const uint2*)(bp + nb * 128);
            uint2 l2 = *(const uint2*)(bp + nb * 128 + 64);
            bh[nb][0] = h2.x; bh[nb][1] = h2.y;
            bl[nb][0] = l2.x; bl[nb][1] = l2.y;
        }

#pragma unroll
        for (int mt = 0; mt < 2; mt++) {
            int r0 = warpRow + mt * 16 + g;
            int r1 = r0 + 8;
            if (r0 >= NN) r0 = NN - 1;
            if (r1 >= NN) r1 = NN - 1;
            // one LDG.128 per row: lane tg holds logical k = 4tg..4tg+3
            float4 q0 = *(const float4*)(src + (size_t)r0 * stride + koff + tg * 4);
            float4 q1 = *(const float4*)(src + (size_t)r1 * stride + koff + tg * 4);
            uint32_t ah[4], al[4];
            split2(make_float2(q0.x, q0.y), ah[0], al[0]);  // frag slot (r0, b0)
            split2(make_float2(q1.x, q1.y), ah[1], al[1]);  // frag slot (r1, b0)
            split2(make_float2(q0.z, q0.w), ah[2], al[2]);  // frag slot (r0, b1)
            split2(make_float2(q1.z, q1.w), ah[3], al[3]);  // frag slot (r1, b1)
#pragma unroll
            for (int nb = 0; nb < 8; nb++) {
                MMA_BF16(acc[mt][nb], ah, bh[nb]);
                MMA_BF16(acc[mt][nb], ah, bl[nb]);
                MMA_BF16(acc[mt][nb], al, bh[nb]);
            }
        }
    }

    // att weights for this lane's columns: ats/atd laid out so index == col
    float ws[8][2], wd[8][2];
#pragma unroll
    for (int nb = 0; nb < 8; nb++) {
        int col = colBase + nb * 8 + tg * 2;
        float2 a = *(const float2*)(ats + col);
        float2 b = *(const float2*)(atd + col);
        ws[nb][0] = a.x; ws[nb][1] = a.y;
        wd[nb][0] = b.x; wd[nb][1] = b.y;
    }

#pragma unroll
    for (int mt = 0; mt < 2; mt++) {
        int r0 = warpRow + mt * 16 + g;
        int r1 = r0 + 8;
        // emit h16
#pragma unroll
        for (int nb = 0; nb < 8; nb++) {
            int col = colBase + nb * 8 + tg * 2;
            if (r0 < NN)
                *(__half2*)(g_h16 + (size_t)r0 * HROW + col) =
                    __floats2half2_rn(acc[mt][nb][0], acc[mt][nb][1]);
            if (r1 < NN)
                *(__half2*)(g_h16 + (size_t)r1 * HROW + col) =
                    __floats2half2_rn(acc[mt][nb][2], acc[mt][nb][3]);
        }
        // fused attention dots: per-head partials, reduced over tg lanes
        float s0[8], d0[8], s1[8], d1[8];
#pragma unroll
        for (int nb = 0; nb < 8; nb++) {
            s0[nb] = acc[mt][nb][0] * ws[nb][0] + acc[mt][nb][1] * ws[nb][1];
            d0[nb] = acc[mt][nb][0] * wd[nb][0] + acc[mt][nb][1] * wd[nb][1];
            s1[nb] = acc[mt][nb][2] * ws[nb][0] + acc[mt][nb][3] * ws[nb][1];
            d1[nb] = acc[mt][nb][2] * wd[nb][0] + acc[mt][nb][3] * wd[nb][1];
        }
        if (CH == 8) {
            // head == nb
#pragma unroll
            for (int nb = 0; nb < 8; nb++) {
#pragma unroll
                for (int dlt = 1; dlt <= 2; dlt <<= 1) {
                    s0[nb] += __shfl_xor_sync(0xffffffffu, s0[nb], dlt);
                    d0[nb] += __shfl_xor_sync(0xffffffffu, d0[nb], dlt);
                    s1[nb] += __shfl_xor_sync(0xffffffffu, s1[nb], dlt);
                    d1[nb] += __shfl_xor_sync(0xffffffffu, d1[nb], dlt);
                }
            }
            if (r0 < NN) {
                g_asrc[r0 * 8 + tg]     = s0[tg];
                g_asrc[r0 * 8 + tg + 4] = s0[tg + 4];
                g_adst[r0 * 8 + tg]     = d0[tg];
                g_adst[r0 * 8 + tg + 4] = d0[tg + 4];
            }
            if (r1 < NN) {
                g_asrc[r1 * 8 + tg]     = s1[tg];
                g_asrc[r1 * 8 + tg + 4] = s1[tg + 4];
                g_adst[r1 * 8 + tg]     = d1[tg];
                g_adst[r1 * 8 + tg + 4] = d1[tg + 4];
            }
        } else {
            // CH == 16: head spans 2 nb; 4 heads per 64-col block
            int headBase = colBase >> 4;
            float hs0[4], hd0[4], hs1[4], hd1[4];
#pragma unroll
            for (int hh = 0; hh < 4; hh++) {
                hs0[hh] = s0[2 * hh] + s0[2 * hh + 1];
                hd0[hh] = d0[2 * hh] + d0[2 * hh + 1];
                hs1[hh] = s1[2 * hh] + s1[2 * hh + 1];
                hd1[hh] = d1[2 * hh] + d1[2 * hh + 1];
#pragma unroll
                for (int dlt = 1; dlt <= 2; dlt <<= 1) {
                    hs0[hh] += __shfl_xor_sync(0xffffffffu, hs0[hh], dlt);
                    hd0[hh] += __shfl_xor_sync(0xffffffffu, hd0[hh], dlt);
                    hs1[hh] += __shfl_xor_sync(0xffffffffu, hs1[hh], dlt);
                    hd1[hh] += __shfl_xor_sync(0xffffffffu, hd1[hh], dlt);
                }
            }
            if (r0 < NN) {
                g_asrc[r0 * 8 + headBase + tg] = hs0[tg];
                g_adst[r0 * 8 + headBase + tg] = hd0[tg];
            }
            if (r1 < NN) {
                g_asrc[r1 * 8 + headBase + tg] = hs1[tg];
                g_adst[r1 * 8 + headBase + tg] = hd1[tg];
            }
        }
    }
}

// ---------------------------------------------------------------------------
// Aggregation, ONE-PASS softmax (logits clamped at 70), fp16 h gather.
// TWO nodes per warp: each 16-lane half-warp owns one node. Lane l (0..15)
// covers 4 (C=8) or 8 (C=16) channels of head l>>1. 4-edge batching per
// half-warp chain -> ~8 independent loads in flight per warp.
// FINAL: head-mean + bias + log_softmax fused (half-warp shuffles).
// ---------------------------------------------------------------------------
template <int C, bool FINAL>
__global__ __launch_bounds__(256) void k_agg(
    const __half* __restrict__ h16,
    const float* __restrict__ bias,
    const float* __restrict__ prelu_a,
    float* __restrict__ out)
{
    constexpr int HROW = C * 8;
    constexpr int VEC = C / 2;  // channels per lane (4 or 8)
    int gwarp = (blockIdx.x * blockDim.x + threadIdx.x) >> 5;
    int lane = threadIdx.x & 31;
    int half = lane >> 4;
    int l = lane & 15;
    int node = gwarp * 2 + half;
    bool valid = node < NN;
    int nodeC = valid ? node : NN - 1;
    int head = l >> 1;

    int beg = g_rowptr[nodeC];
    int end = g_rowptr[nodeC + 1];
    float ad = g_adst[nodeC * 8 + head];

    float ssum = 0.f;
    float acc[VEC];
#pragma unroll
    for (int j = 0; j < VEC; j++) acc[j] = 0.f;

    int i = beg;
    for (; i + 4 <= end; i += 4) {
        int s[4];
#pragma unroll
        for (int u = 0; u < 4; u++) s[u] = g_csrc[i + u];
        float a[4];
#pragma unroll
        for (int u = 0; u < 4; u++) a[u] = g_asrc[s[u] * 8 + head];
        uint2 p2[4];   // C==8 payload (4 halfs)
        uint4 p4[4];   // C==16 payload (8 halfs)
#pragma unroll
        for (int u = 0; u < 4; u++) {
            if (!FINAL)
                p2[u] = *(const uint2*)(h16 + (size_t)s[u] * HROW + l * 4);
            else
                p4[u] = *(const uint4*)(h16 + (size_t)s[u] * HROW + l * 8);
        }
#pragma unroll
        for (int u = 0; u < 4; u++) {
            float e = a[u] + ad;
            e = (e < 0.f) ? 0.2f * e : e;
            float w = __expf(fminf(e, 70.f));
            ssum += w;
            if (!FINAL) {
                float2 qa = __half22float2(*(__half2*)&p2[u].x);
                float2 qb = __half22float2(*(__half2*)&p2[u].y);
                acc[0] += w * qa.x;
                acc[1] += w * qa.y;
                acc[2] += w * qb.x;
                acc[3] += w * qb.y;
            } else {
                float2 qa = __half22float2(*(__half2*)&p4[u].x);
                float2 qb = __half22float2(*(__half2*)&p4[u].y);
                float2 qc = __half22float2(*(__half2*)&p4[u].z);
                float2 qd = __half22float2(*(__half2*)&p4[u].w);
                acc[0] += w * qa.x;
                acc[1] += w * qa.y;
                acc[2] += w * qb.x;
                acc[3] += w * qb.y;
                acc[4] += w * qc.x;
                acc[5] += w * qc.y;
                acc[6] += w * qd.x;
                acc[7] += w * qd.y;
            }
        }
    }
    for (; i < end; ++i) {
        int s0 = g_csrc[i];
        float a0 = g_asrc[s0 * 8 + head];
        float e0 = a0 + ad; e0 = (e0 < 0.f) ? 0.2f * e0 : e0;
        float w0 = __expf(fminf(e0, 70.f));
        ssum += w0;
        if (!FINAL) {
            uint2 u0 = *(const uint2*)(h16 + (size_t)s0 * HROW + l * 4);
            float2 qa = __half22float2(*(__half2*)&u0.x);
            float2 qb = __half22float2(*(__half2*)&u0.y);
            acc[0] += w0 * qa.x;
            acc[1] += w0 * qa.y;
            acc[2] += w0 * qb.x;
            acc[3] += w0 * qb.y;
        } else {
            uint4 u0 = *(const uint4*)(h16 + (size_t)s0 * HROW + l * 8);
            float2 qa = __half22float2(*(__half2*)&u0.x);
            float2 qb = __half22float2(*(__half2*)&u0.y);
            float2 qc = __half22float2(*(__half2*)&u0.z);
            float2 qd = __half22float2(*(__half2*)&u0.w);
            acc[0] += w0 * qa.x;
            acc[1] += w0 * qa.y;
            acc[2] += w0 * qb.x;
            acc[3] += w0 * qb.y;
            acc[4] += w0 * qc.x;
            acc[5] += w0 * qc.y;
            acc[6] += w0 * qd.x;
            acc[7] += w0 * qd.y;
        }
    }
    float inv = 1.f / (ssum + 1e-16f);

    if (!FINAL) {
        float p = prelu_a[0];
        float4 b4 = *(const float4*)(bias + l * 4);
        float v0 = acc[0] * inv + b4.x;
        float v1 = acc[1] * inv + b4.y;
        float v2 = acc[2] * inv + b4.z;
        float v3 = acc[3] * inv + b4.w;
        v0 = (v0 >= 0.f) ? v0 : p * v0;
        v1 = (v1 >= 0.f) ? v1 : p * v1;
        v2 = (v2 >= 0.f) ? v2 : p * v2;
        v3 = (v3 >= 0.f) ? v3 : p * v3;
        if (valid)
            *(float4*)(out + (size_t)node * 64 + l * 4) =
                make_float4(v0, v1, v2, v3);
    } else {
        // mean over heads: lane l covers out-channels (l&1)*8 + j.
        // Heads = l>>1; reduce over l-bits 1..3 (stays within 16-lane half).
        float v[8];
#pragma unroll
        for (int j = 0; j < 8; j++) {
            v[j] = acc[j] * inv;
            v[j] += __shfl_xor_sync(0xffffffffu, v[j], 2);
            v[j] += __shfl_xor_sync(0xffffffffu, v[j], 4);
            v[j] += __shfl_xor_sync(0xffffffffu, v[j], 8);
            v[j] = v[j] * 0.125f + bias[(l & 1) * 8 + j];
        }
        // log_softmax over 16 channels, split lane pair (l=0: 0-7, l=1: 8-15)
        float mx = v[0];
#pragma unroll
        for (int j = 1; j < 8; j++) mx = fmaxf(mx, v[j]);
        mx = fmaxf(mx, __shfl_xor_sync(0xffffffffu, mx, 1));
        float se = 0.f;
#pragma unroll
        for (int j = 0; j < 8; j++) se += __expf(v[j] - mx);
        se += __shfl_xor_sync(0xffffffffu, se, 1);
        float lse = mx + __logf(se);
        if (valid && l < 2) {
            float* op = out + (size_t)node * 16 + l * 8;
            *(float4*)op = make_float4(v[0] - lse, v[1] - lse,
                                       v[2] - lse, v[3] - lse);
            *(float4*)(op + 4) = make_float4(v[4] - lse, v[5] - lse,
                                             v[6] - lse, v[7] - lse);
        }
    }
}

// ---------------------------------------------------------------------------
// Launch
// ---------------------------------------------------------------------------
extern "C" void kernel_launch(void* const* d_in, const int* in_sizes, int n_in,
                              void* d_out, int out_size)
{
    const float* x   = (const float*)d_in[0];
    const int*   ei  = (const int*)d_in[1];
    const float* W1  = (const float*)d_in[2];
    const float* as1 = (const float*)d_in[3];
    const float* ad1 = (const float*)d_in[4];
    const float* b1  = (const float*)d_in[5];
    const float* W2  = (const float*)d_in[6];
    const float* as2 = (const float*)d_in[7];
    const float* ad2 = (const float*)d_in[8];
    const float* b2  = (const float*)d_in[9];
    const float* W3  = (const float*)d_in[10];
    const float* as3 = (const float*)d_in[11];
    const float* ad3 = (const float*)d_in[12];
    const float* b3  = (const float*)d_in[13];
    const float* p1  = (const float*)d_in[14];
    const float* p2  = (const float*)d_in[15];
    float* out = (float*)d_out;

    void *po, *ph16, *pb1, *pb2, *pb3;
    cudaGetSymbolAddress(&po, g_out);
    cudaGetSymbolAddress(&ph16, g_h16);
    cudaGetSymbolAddress(&pb1, g_bf1);
    cudaGetSymbolAddress(&pb2, g_bf2);
    cudaGetSymbolAddress(&pb3, g_bf3);
    float* o = (float*)po;
    const __half* h16 = (const __half*)ph16;

    const int* esrc = ei;
    const int* edst = ei + NE;

    int agg_blocks = (NN + 15) / 16;   // 16 nodes per 256-thr block
    dim3 gg1((NN + 255) / 256, 1);     // 391 CTAs of 256 threads
    dim3 gg3((NN + 255) / 256, 2);

    // Launch order puts gemm1 at position 4 (ncu -s 5 -c 1 capture window).
    k_deg_init<<<(NN + 255) / 256, 256>>>();                              // 1
    k_hist<<<(NE + 255) / 256, 256>>>(edst);                              // 2
    k_wfrag<<<(45056 + 255) / 256, 256>>>(W1, W2, W3);                    // 3

    // Layer-1 GEMM (independent of CSR)
    k_gemm_mma<8, 64, 8><<<gg1, 256>>>(x, 256, (const float*)0, 0,        // 4
                                       (const uint32_t*)pb1, as1, ad1);

    // CSR scan + scatter (coalesced two-level scan)
    k_scan_a<<<SCAN_TILES, SCAN_T>>>();                                   // 5
    k_scan_b<<<1, 256>>>();                                               // 6
    k_scan_c<<<SCAN_TILES, SCAN_T>>>();                                   // 7
    k_scatter<<<(NN + NE + 255) / 256, 256>>>(esrc, edst);                // 8

    // Layer 1 aggregate ; +b1 ; PReLU(p1)
    k_agg<8, false><<<agg_blocks, 256>>>(h16, b1, p1, o);                 // 9

    // Layer 2
    k_gemm_mma<8, 64, 8><<<gg1, 256>>>(x, 256, o, 64,
                                       (const uint32_t*)pb2, as2, ad2);
    k_agg<8, false><<<agg_blocks, 256>>>(h16, b2, p2, o);

    // Layer 3
    k_gemm_mma<16, 128, 16><<<gg3, 256>>>(o, 64, (const float*)0, 0,
                                          (const uint32_t*)pb3, as3, ad3);
    k_agg<16, true><<<agg_blocks, 256>>>(h16, b3, (const float*)0, out);
}